// round 9
// baseline (speedup 1.0000x reference)
#include <cuda_runtime.h>
#include <cuda_bf16.h>
#include <cstdint>

// ---------------------------------------------------------------------------
// CrystalDecoder on GB300 (sm_103a via compute_103 PTX -> HMMA mma.sync only)
// Node path: 16-warp pair-autonomous compensated mma.sync GEMM with a dynamic
//            work queue that INTERLEAVES edge-gather units (1 per 32 tickets)
//            so latency-bound gather hides under tensor-bound node work.
// Edge path: 256x256 lookup table + uint8-gid gather units.
// ---------------------------------------------------------------------------

#define MAXB 256

__device__ float  g_zb[MAXB * 64];      // z_proj @ nd1_w + nd1_b
__device__ float  g_As[MAXB * 64];
__device__ float  g_Bd[MAXB * 64];
__device__ float4 g_table[MAXB * MAXB];
__device__ int    g_ctr;                // dynamic work-queue ticket
__device__ uint8_t g_gid8[262144];      // uint8 graph_id (fits L1)

// transposed weights, bf16 hi/lo: W1^T [128 n][128 k], W2^T [64 n][128 k]
__device__ uint16_t g_w1thi[128 * 128];
__device__ uint16_t g_w1tlo[128 * 128];
__device__ uint16_t g_w2thi[64 * 128];
__device__ uint16_t g_w2tlo[64 * 128];

#define XS 68
#define NODE_GRID 148
#define NPAIRS (NODE_GRID * 8)
#define GCH 4096                 // edges per gather unit

#define MMA16816(c, a, b0, b1) \
    asm volatile("mma.sync.aligned.m16n8k16.row.col.f32.bf16.bf16.f32 " \
        "{%0,%1,%2,%3}, {%4,%5,%6,%7}, {%8,%9}, {%0,%1,%2,%3};" \
        : "+f"((c)[0]), "+f"((c)[1]), "+f"((c)[2]), "+f"((c)[3]) \
        : "r"((a)[0]), "r"((a)[1]), "r"((a)[2]), "r"((a)[3]), "r"(b0), "r"(b1))

#define PAIR_BAR(id) asm volatile("bar.sync %0, 64;" :: "r"(id) : "memory")

// ticket mapping: every 32nd ticket (t%32==31) is a gather unit
__device__ __forceinline__ bool is_node_t(int t) { return (t & 31) != 31; }

// truncation hi/lo split: hi = top-16 bits (exact bf16), lo = rn(x - hi)
__device__ __forceinline__ void tsplit2(float x0, float x1, uint32_t& hi, uint32_t& lo) {
    uint32_t u0 = __float_as_uint(x0), u1 = __float_as_uint(x1);
    hi = __byte_perm(u0, u1, 0x7632);
    float h0 = __uint_as_float(u0 & 0xFFFF0000u);
    float h1 = __uint_as_float(u1 & 0xFFFF0000u);
    float l0 = x0 - h0, l1 = x1 - h1;
    asm("cvt.rn.bf16x2.f32 %0, %1, %2;" : "=r"(lo) : "f"(l1), "f"(l0));
}

// ---------------------------------------------------------------------------
// Fused prep + weight conversion + gid8 + queue reset.
// ---------------------------------------------------------------------------
__global__ void prep_wconv_kernel(const float* __restrict__ z,
                            const float* __restrict__ lp_w, const float* __restrict__ lp_b,
                            const float* __restrict__ nd1_w, const float* __restrict__ nd1_b,
                            const float* __restrict__ ed1_w,
                            const float* __restrict__ en1_w, const float* __restrict__ en1_b,
                            const float* __restrict__ en2_w, const float* __restrict__ en2_b,
                            const float* __restrict__ st1_w, const float* __restrict__ st1_b,
                            const float* __restrict__ st2_w, const float* __restrict__ st2_b,
                            const float* __restrict__ nep_w,
                            const int* __restrict__ graph_id, int N,
                            float* __restrict__ out_energy, float* __restrict__ out_stress,
                            int B)
{
    const int t = threadIdx.x;
    if (blockIdx.x >= B) {
        int j0 = (blockIdx.x - B) * 128 + t;        // 0..6143
        if (blockIdx.x == B && t == 0) g_ctr = NPAIRS;
        for (int i = j0; i < 128 * 128; i += 6144) {
            int k = i >> 7, n = i & 127;
            float v = nep_w[k * 128 + n];
            __nv_bfloat16 hh = __float2bfloat16(v);
            __nv_bfloat16 ll = __float2bfloat16(v - __bfloat162float(hh));
            g_w1thi[n * 128 + k] = *(uint16_t*)&hh;
            g_w1tlo[n * 128 + k] = *(uint16_t*)&ll;
        }
        for (int i = j0; i < 64 * 128; i += 6144) {
            int k = i >> 6, n = i & 63;
            float v = nd1_w[k * 64 + n];
            __nv_bfloat16 hh = __float2bfloat16(v);
            __nv_bfloat16 ll = __float2bfloat16(v - __bfloat162float(hh));
            g_w2thi[n * 128 + k] = *(uint16_t*)&hh;
            g_w2tlo[n * 128 + k] = *(uint16_t*)&ll;
        }
        for (int i = j0; i < N; i += 6144)
            g_gid8[i] = (uint8_t)graph_id[i];
        return;
    }

    const int b = blockIdx.x;
    __shared__ float zrow[32];
    __shared__ float zp[128];
    __shared__ float eh[64], sh[64];

    if (t < 32) zrow[t] = z[b * 32 + t];
    __syncthreads();
    {
        float acc = lp_b[t];
        #pragma unroll
        for (int k = 0; k < 32; k++) acc = fmaf(zrow[k], lp_w[k * 128 + t], acc);
        zp[t] = fmaxf(acc, 0.f);
    }
    if (t < 64) {
        float a1 = en1_b[t], a2 = st1_b[t];
        #pragma unroll
        for (int k = 0; k < 32; k++) {
            float zv = zrow[k];
            a1 = fmaf(zv, en1_w[k * 64 + t], a1);
            a2 = fmaf(zv, st1_w[k * 64 + t], a2);
        }
        eh[t] = fmaxf(a1, 0.f);
        sh[t] = fmaxf(a2, 0.f);
    }
    __syncthreads();
    if (t < 64) {
        float as = 0.f, bd = 0.f, zb = nd1_b[t];
        #pragma unroll 4
        for (int k = 0; k < 128; k++) {
            float zv = zp[k];
            as = fmaf(zv, ed1_w[k * 64 + t], as);
            bd = fmaf(zv, ed1_w[(128 + k) * 64 + t], bd);
            zb = fmaf(zv, nd1_w[k * 64 + t], zb);
        }
        g_As[b * 64 + t] = as;
        g_Bd[b * 64 + t] = bd;
        g_zb[b * 64 + t] = zb;
    }
    if (t < 2) {
        float a = en2_b[t];
        #pragma unroll 8
        for (int k = 0; k < 64; k++) a = fmaf(eh[k], en2_w[k * 2 + t], a);
        out_energy[b * 2 + t] = a;
    }
    if (t >= 16 && t < 25) {
        int j = t - 16;
        float a = st2_b[j];
        #pragma unroll 8
        for (int k = 0; k < 64; k++) a = fmaf(sh[k], st2_w[k * 9 + j], a);
        out_stress[b * 9 + j] = a;
    }
}

// ---------------------------------------------------------------------------
// Edge table
// ---------------------------------------------------------------------------
__global__ void edge_table_kernel(const float* __restrict__ ed1_b,
                                  const float* __restrict__ ed2_w,
                                  const float* __restrict__ ed2_b)
{
    const int gs = blockIdx.x;
    const int gd = threadIdx.x;
    __shared__ float sAs[64], sb1[64], sw2[64 * 3], sb2[3];
    const int t = threadIdx.x;
    if (t < 64) { sAs[t] = g_As[gs * 64 + t]; sb1[t] = ed1_b[t]; }
    if (t >= 64 && t < 64 + 192) sw2[t - 64] = ed2_w[t - 64];
    if (t < 3) sb2[t] = ed2_b[t];
    __syncthreads();

    float o0 = sb2[0], o1 = sb2[1], o2 = sb2[2];
    const float4* bd4 = (const float4*)(&g_Bd[gd * 64]);
    #pragma unroll
    for (int k4 = 0; k4 < 16; k4++) {
        float4 bv = bd4[k4];
        int k = k4 * 4;
        float h;
        h = fmaxf(sAs[k + 0] + bv.x + sb1[k + 0], 0.f);
        o0 = fmaf(h, sw2[(k + 0) * 3 + 0], o0); o1 = fmaf(h, sw2[(k + 0) * 3 + 1], o1); o2 = fmaf(h, sw2[(k + 0) * 3 + 2], o2);
        h = fmaxf(sAs[k + 1] + bv.y + sb1[k + 1], 0.f);
        o0 = fmaf(h, sw2[(k + 1) * 3 + 0], o0); o1 = fmaf(h, sw2[(k + 1) * 3 + 1], o1); o2 = fmaf(h, sw2[(k + 1) * 3 + 2], o2);
        h = fmaxf(sAs[k + 2] + bv.z + sb1[k + 2], 0.f);
        o0 = fmaf(h, sw2[(k + 2) * 3 + 0], o0); o1 = fmaf(h, sw2[(k + 2) * 3 + 1], o1); o2 = fmaf(h, sw2[(k + 2) * 3 + 2], o2);
        h = fmaxf(sAs[k + 3] + bv.w + sb1[k + 3], 0.f);
        o0 = fmaf(h, sw2[(k + 3) * 3 + 0], o0); o1 = fmaf(h, sw2[(k + 3) * 3 + 1], o1); o2 = fmaf(h, sw2[(k + 3) * 3 + 2], o2);
    }
    g_table[gs * MAXB + gd] = make_float4(o0, o1, o2, 0.f);
}

// ---------------------------------------------------------------------------
// Persistent node+gather kernel: 512 threads, 8 autonomous pairs, one queue.
// Ticket t: (t%32==31) -> gather unit t/32 (GCH edges);
//           else       -> node unit t - t/32 (16 rows).
// Over-range units are guard-skipped (harmless).
// ---------------------------------------------------------------------------
#define NODE_SMEM_U32 (2*128*XS + 2*64*XS + 2*128*XS + 128 + 256 + 8)
#define NODE_SMEM_BYTES (NODE_SMEM_U32 * 4)

__global__ void __launch_bounds__(512, 1)
node_mma_kernel(const float* __restrict__ node_emb, const int* __restrict__ graph_id,
                const float* __restrict__ b1,
                const float* __restrict__ w3, const float* __restrict__ b3,
                float* __restrict__ out_node, int N, int T,
                const int* __restrict__ src, const int* __restrict__ dst,
                float* __restrict__ out_edge, int E)
{
    extern __shared__ uint32_t su[];
    uint32_t* sW1h = su;                        // [128][XS]
    uint32_t* sW1l = sW1h + 128 * XS;
    uint32_t* sW2h = sW1l + 128 * XS;           // [64][XS]
    uint32_t* sW2l = sW2h + 64 * XS;
    uint32_t* sXh  = sW2l + 64 * XS;            // [128][XS]
    uint32_t* sXl  = sXh + 128 * XS;            // [128][XS]; merge aliases pair rows
    float*    sB1  = (float*)(sXl + 128 * XS);  // [128]
    float*    sW3  = sB1 + 128;                 // [64][4]
    int*      sNU  = (int*)(sW3 + 256);         // [8] next-ticket per pair

    const int tid  = threadIdx.x;
    const int lane = tid & 31;
    const int w    = tid >> 5;       // 0..15
    const int p    = w >> 1;         // pair 0..7
    const int h    = w & 1;          // half
    const int g    = lane >> 2;
    const int tg   = lane & 3;
    const int r0   = p * 16;
    const int u    = tid & 63;       // thread within pair
    const int barid = p + 1;
    const int rloc = g + (h ? 8 : 0);           // local row this warp finalizes
    float* mrg = (float*)(sXl + p * 1088);      // 4KB inside own pair's sXl rows

    // ---- one-time staging (block-wide) ----
    for (int i = tid; i < 128 * 64; i += 512) {
        int n = i >> 6, kp = i & 63;
        sW1h[n * XS + kp] = ((const uint32_t*)g_w1thi)[i];
        sW1l[n * XS + kp] = ((const uint32_t*)g_w1tlo)[i];
    }
    for (int i = tid; i < 64 * 64; i += 512) {
        int n = i >> 6, kp = i & 63;
        sW2h[n * XS + kp] = ((const uint32_t*)g_w2thi)[i];
        sW2l[n * XS + kp] = ((const uint32_t*)g_w2tlo)[i];
    }
    if (tid < 128) sB1[tid] = b1[tid];
    else if (tid >= 256 && tid < 320) ((float4*)sW3)[tid - 256] = ((const float4*)w3)[tid - 256];
    const float b30 = b3[0], b31 = b3[1], b32 = b3[2], b33 = b3[3];

    // ---- prologue: stage this pair's first unit (if node-type) ----
    int ticket = blockIdx.x * 8 + p;
    if (ticket < T && is_node_t(ticket)) {
        const int gbase = (ticket - (ticket >> 5)) * 16;
        #pragma unroll
        for (int it = 0; it < 8; it++) {
            int idx = it * 64 + u;
            int rl  = idx >> 5;              // 0..15
            int q   = idx & 31;
            int gn  = gbase + rl;
            float4 v = (gn < N) ? ((const float4*)(node_emb + (size_t)gn * 128))[q]
                                : make_float4(0.f, 0.f, 0.f, 0.f);
            uint32_t h0v, l0v, h1v, l1v;
            tsplit2(v.x, v.y, h0v, l0v);
            tsplit2(v.z, v.w, h1v, l1v);
            *(uint2*)&sXh[(r0 + rl) * XS + 2 * q] = make_uint2(h0v, h1v);
            *(uint2*)&sXl[(r0 + rl) * XS + 2 * q] = make_uint2(l0v, l1v);
        }
    }
    __syncthreads();   // only block-wide sync

    while (ticket < T) {
        // grab next ticket early; latency hidden under this unit's work
        if (h == 0 && lane == 0) sNU[p] = atomicAdd(&g_ctr, 1);

        if (is_node_t(ticket)) {
            // =================== NODE UNIT ===================
            const int gbase = (ticket - (ticket >> 5)) * 16;
            const int grow = gbase + rloc;
            const int gid = graph_id[(grow < N) ? grow : (N - 1)];

            // ---- Layer 1 ----
            float acc[8][4];
            #pragma unroll
            for (int j = 0; j < 8; j++)
                #pragma unroll
                for (int q = 0; q < 4; q++) acc[j][q] = 0.f;

            const uint32_t* xh0 = &sXh[(r0 + g) * XS];
            const uint32_t* xh1 = &sXh[(r0 + g + 8) * XS];
            const uint32_t* xl0 = &sXl[(r0 + g) * XS];
            const uint32_t* xl1 = &sXl[(r0 + g + 8) * XS];

            #pragma unroll
            for (int s = 0; s < 8; s++) {
                const int o = s * 8 + tg;
                uint32_t aH[4] = { xh0[o], xh1[o], xh0[o + 4], xh1[o + 4] };
                uint32_t aL[4] = { xl0[o], xl1[o], xl0[o + 4], xl1[o + 4] };
                #pragma unroll
                for (int j = 0; j < 8; j++) {
                    const int nrow = ((8 * h + j) * 8 + g) * XS;
                    uint32_t bh0 = sW1h[nrow + o], bh1 = sW1h[nrow + o + 4];
                    uint32_t bl0 = sW1l[nrow + o], bl1 = sW1l[nrow + o + 4];
                    MMA16816(acc[j], aH, bh0, bh1);
                    MMA16816(acc[j], aH, bl0, bl1);
                    MMA16816(acc[j], aL, bh0, bh1);
                }
            }
            PAIR_BAR(barid);   // barA: sX reads done; sNU visible

            const int  ntick = sNU[p];
            const bool nv    = (ntick < T) && is_node_t(ntick);
            float4 xp[8];
            if (nv) {
                const int nbase = (ntick - (ntick >> 5)) * 16;
                #pragma unroll
                for (int it = 0; it < 8; it++) {
                    int idx = it * 64 + u;
                    int gn  = nbase + (idx >> 5);
                    xp[it] = (gn < N) ? ((const float4*)(node_emb + (size_t)gn * 128))[idx & 31]
                                      : make_float4(0.f, 0.f, 0.f, 0.f);
                }
            }

            // ---- epilogue 1 -> A2 frags ----
            uint32_t a2h[4][4], a2l[4][4];
            #pragma unroll
            for (int s2 = 0; s2 < 4; s2++) {
                int cA = (4 * h + s2) * 16 + tg * 2;
                int cB = cA + 8;
                float bA0 = sB1[cA], bA1 = sB1[cA + 1];
                float bB0 = sB1[cB], bB1 = sB1[cB + 1];
                tsplit2(fmaxf(acc[2 * s2][0] + bA0, 0.f),
                        fmaxf(acc[2 * s2][1] + bA1, 0.f), a2h[s2][0], a2l[s2][0]);
                tsplit2(fmaxf(acc[2 * s2][2] + bA0, 0.f),
                        fmaxf(acc[2 * s2][3] + bA1, 0.f), a2h[s2][1], a2l[s2][1]);
                tsplit2(fmaxf(acc[2 * s2 + 1][0] + bB0, 0.f),
                        fmaxf(acc[2 * s2 + 1][1] + bB1, 0.f), a2h[s2][2], a2l[s2][2]);
                tsplit2(fmaxf(acc[2 * s2 + 1][2] + bB0, 0.f),
                        fmaxf(acc[2 * s2 + 1][3] + bB1, 0.f), a2h[s2][3], a2l[s2][3]);
            }

            // ---- Layer 2: local k-half ----
            float acc2[8][4];
            #pragma unroll
            for (int j = 0; j < 8; j++)
                #pragma unroll
                for (int q = 0; q < 4; q++) acc2[j][q] = 0.f;

            #pragma unroll
            for (int s = 0; s < 4; s++) {
                const int o = (4 * h + s) * 8 + tg;
                #pragma unroll
                for (int j = 0; j < 8; j++) {
                    const int nrow = (j * 8 + g) * XS;
                    uint32_t bh0 = sW2h[nrow + o], bh1 = sW2h[nrow + o + 4];
                    uint32_t bl0 = sW2l[nrow + o], bl1 = sW2l[nrow + o + 4];
                    MMA16816(acc2[j], a2h[s], bh0, bh1);
                    MMA16816(acc2[j], a2h[s], bl0, bl1);
                    MMA16816(acc2[j], a2l[s], bh0, bh1);
                }
            }

            // ---- zb prefetch ----
            float2 zbv[8];
            {
                const float2* zp2 = (const float2*)(g_zb + gid * 64);
                #pragma unroll
                for (int nt = 0; nt < 8; nt++) zbv[nt] = zp2[nt * 4 + tg];
            }

            // ---- balanced merge ----
            {
                float* dstp = mrg + (h ? 512 : 0);
                int qo = h ? 0 : 2;
                #pragma unroll
                for (int j = 0; j < 8; j++) {
                    dstp[(j * 2 + 0) * 32 + lane] = acc2[j][qo + 0];
                    dstp[(j * 2 + 1) * 32 + lane] = acc2[j][qo + 1];
                }
            }
            PAIR_BAR(barid);   // barB

            {
                const float* srcp = mrg + (h ? 0 : 512);
                int qo = h ? 2 : 0;
                float o0 = 0.f, o1 = 0.f, o2 = 0.f, o3 = 0.f;
                #pragma unroll
                for (int nt = 0; nt < 8; nt++) {
                    float v0 = acc2[nt][qo + 0] + srcp[(nt * 2 + 0) * 32 + lane];
                    float v1 = acc2[nt][qo + 1] + srcp[(nt * 2 + 1) * 32 + lane];
                    float hv0 = fmaxf(v0 + zbv[nt].x, 0.f);
                    float hv1 = fmaxf(v1 + zbv[nt].y, 0.f);
                    int c0 = nt * 8 + tg * 2;
                    float4 w0 = *(const float4*)&sW3[c0 * 4];
                    float4 w1 = *(const float4*)&sW3[(c0 + 1) * 4];
                    o0 = fmaf(hv0, w0.x, fmaf(hv1, w1.x, o0));
                    o1 = fmaf(hv0, w0.y, fmaf(hv1, w1.y, o1));
                    o2 = fmaf(hv0, w0.z, fmaf(hv1, w1.z, o2));
                    o3 = fmaf(hv0, w0.w, fmaf(hv1, w1.w, o3));
                }
                #pragma unroll
                for (int d = 1; d <= 2; d <<= 1) {
                    o0 += __shfl_xor_sync(0xFFFFFFFF, o0, d);
                    o1 += __shfl_xor_sync(0xFFFFFFFF, o1, d);
                    o2 += __shfl_xor_sync(0xFFFFFFFF, o2, d);
                    o3 += __shfl_xor_sync(0xFFFFFFFF, o3, d);
                }
                if (tg == 0 && grow < N)
                    *(float4*)&out_node[(size_t)grow * 4] =
                        make_float4(o0 + b30, o1 + b31, o2 + b32, o3 + b33);
            }

            // ---- stage next X hi/lo (only if next is node) ----
            if (nv) {
                #pragma unroll
                for (int it = 0; it < 8; it++) {
                    int idx = it * 64 + u;
                    int rl  = idx >> 5;
                    int q   = idx & 31;
                    float4 v = xp[it];
                    uint32_t h0v, l0v, h1v, l1v;
                    tsplit2(v.x, v.y, h0v, l0v);
                    tsplit2(v.z, v.w, h1v, l1v);
                    *(uint2*)&sXh[(r0 + rl) * XS + 2 * q] = make_uint2(h0v, h1v);
                }
            }
            PAIR_BAR(barid);   // barC

            if (nv) {
                #pragma unroll
                for (int it = 0; it < 8; it++) {
                    int idx = it * 64 + u;
                    int rl  = idx >> 5;
                    int q   = idx & 31;
                    float4 v = xp[it];
                    uint32_t h0v, l0v, h1v, l1v;
                    tsplit2(v.x, v.y, h0v, l0v);
                    tsplit2(v.z, v.w, h1v, l1v);
                    *(uint2*)&sXl[(r0 + rl) * XS + 2 * q] = make_uint2(l0v, l1v);
                }
            }
            PAIR_BAR(barid);   // barD
            ticket = ntick;
        } else {
            // =================== GATHER UNIT ===================
            const int gu = ticket >> 5;
            const int ebase = gu * GCH + u * 4;
            #pragma unroll 4
            for (int it = 0; it < GCH / 256; it++) {
                int e = ebase + it * 256;
                if (e + 4 <= E) {
                    int4 s = *(const int4*)(src + e);
                    int4 d = *(const int4*)(dst + e);
                    int gs0 = g_gid8[s.x], gs1 = g_gid8[s.y], gs2 = g_gid8[s.z], gs3 = g_gid8[s.w];
                    int gd0 = g_gid8[d.x], gd1 = g_gid8[d.y], gd2 = g_gid8[d.z], gd3 = g_gid8[d.w];
                    float4 t0 = g_table[gs0 * MAXB + gd0];
                    float4 t1 = g_table[gs1 * MAXB + gd1];
                    float4 t2 = g_table[gs2 * MAXB + gd2];
                    float4 t3 = g_table[gs3 * MAXB + gd3];
                    float* o = out_edge + (size_t)e * 3;
                    ((float4*)o)[0] = make_float4(t0.x, t0.y, t0.z, t1.x);
                    ((float4*)o)[1] = make_float4(t1.y, t1.z, t2.x, t2.y);
                    ((float4*)o)[2] = make_float4(t2.z, t3.x, t3.y, t3.z);
                } else if (e < E) {
                    for (int q = e; q < E; q++) {
                        float4 tv = g_table[g_gid8[src[q]] * MAXB + g_gid8[dst[q]]];
                        out_edge[(size_t)q * 3 + 0] = tv.x;
                        out_edge[(size_t)q * 3 + 1] = tv.y;
                        out_edge[(size_t)q * 3 + 2] = tv.z;
                    }
                }
            }
            PAIR_BAR(barid);   // sNU visible; prior sX readers long done

            const int  ntick = sNU[p];
            const bool nv    = (ntick < T) && is_node_t(ntick);
            if (nv) {
                const int nbase = (ntick - (ntick >> 5)) * 16;
                #pragma unroll
                for (int it = 0; it < 8; it++) {
                    int idx = it * 64 + u;
                    int rl  = idx >> 5;
                    int q   = idx & 31;
                    int gn  = nbase + rl;
                    float4 v = (gn < N) ? ((const float4*)(node_emb + (size_t)gn * 128))[q]
                                        : make_float4(0.f, 0.f, 0.f, 0.f);
                    uint32_t h0v, l0v, h1v, l1v;
                    tsplit2(v.x, v.y, h0v, l0v);
                    tsplit2(v.z, v.w, h1v, l1v);
                    *(uint2*)&sXh[(r0 + rl) * XS + 2 * q] = make_uint2(h0v, h1v);
                    *(uint2*)&sXl[(r0 + rl) * XS + 2 * q] = make_uint2(l0v, l1v);
                }
            }
            PAIR_BAR(barid);   // staging complete before next node L1
            ticket = ntick;
        }
    }
}

// ---------------------------------------------------------------------------
extern "C" void kernel_launch(void* const* d_in, const int* in_sizes, int n_in,
                              void* d_out, int out_size)
{
    const float* z        = (const float*)d_in[0];
    const float* node_emb = (const float*)d_in[1];
    const int*   graph_id = (const int*)  d_in[2];
    const int*   src      = (const int*)  d_in[3];
    const int*   dst      = (const int*)  d_in[4];
    const float* lp_w  = (const float*)d_in[5];
    const float* lp_b  = (const float*)d_in[6];
    const float* nep_w = (const float*)d_in[7];
    const float* nep_b = (const float*)d_in[8];
    const float* nd1_w = (const float*)d_in[9];
    const float* nd1_b = (const float*)d_in[10];
    const float* nd2_w = (const float*)d_in[11];
    const float* nd2_b = (const float*)d_in[12];
    const float* ed1_w = (const float*)d_in[13];
    const float* ed1_b = (const float*)d_in[14];
    const float* ed2_w = (const float*)d_in[15];
    const float* ed2_b = (const float*)d_in[16];
    const float* en1_w = (const float*)d_in[17];
    const float* en1_b = (const float*)d_in[18];
    const float* en2_w = (const float*)d_in[19];
    const float* en2_b = (const float*)d_in[20];
    const float* st1_w = (const float*)d_in[21];
    const float* st1_b = (const float*)d_in[22];
    const float* st2_w = (const float*)d_in[23];
    const float* st2_b = (const float*)d_in[24];

    const int B = in_sizes[0] / 32;
    const int N = in_sizes[1] / 128;
    const int E = in_sizes[3];

    float* out        = (float*)d_out;
    float* out_node   = out;
    float* out_edge   = out + (size_t)N * 4;
    float* out_energy = out + (size_t)N * 4 + (size_t)E * 3;
    float* out_stress = out_energy + (size_t)B * 2;

    cudaFuncSetAttribute(node_mma_kernel, cudaFuncAttributeMaxDynamicSharedMemorySize,
                         NODE_SMEM_BYTES);

    prep_wconv_kernel<<<B + 48, 128>>>(z, lp_w, lp_b, nd1_w, nd1_b, ed1_w,
                                       en1_w, en1_b, en2_w, en2_b,
                                       st1_w, st1_b, st2_w, st2_b,
                                       nep_w, graph_id, N,
                                       out_energy, out_stress, B);

    edge_table_kernel<<<B, 256>>>(ed1_b, ed2_w, ed2_b);

    const int U_node = (N + 15) / 16;
    const int U_g    = (E + GCH - 1) / GCH;
    int T1 = U_node + U_node / 31 + 33;   // covers all node units (every 32nd is gather)
    int T2 = 32 * U_g;                    // covers all gather units
    const int T = (T1 > T2) ? T1 : T2;

    node_mma_kernel<<<NODE_GRID, 512, NODE_SMEM_BYTES>>>(node_emb, graph_id,
                                                         nep_b, nd2_w, nd2_b,
                                                         out_node, N, T,
                                                         src, dst, out_edge, E);
}

// round 10
// speedup vs baseline: 1.0231x; 1.0231x over previous
#include <cuda_runtime.h>
#include <cuda_bf16.h>
#include <cstdint>

// ---------------------------------------------------------------------------
// CrystalDecoder on GB300 (sm_103a via compute_103 PTX -> HMMA mma.sync only)
// Node path: 16-warp pair-autonomous compensated mma.sync GEMM, dynamic queue,
//            in-CTA weight conversion (no global bf16 weight round-trip).
// Edge path: 256x256 lookup table + uint8-gid gather.
// ---------------------------------------------------------------------------

#define MAXB 256

__device__ float  g_zb[MAXB * 64];      // z_proj @ nd1_w + nd1_b
__device__ float  g_As[MAXB * 64];
__device__ float  g_Bd[MAXB * 64];
__device__ float4 g_table[MAXB * MAXB];
__device__ int    g_ctr;                // dynamic work-queue ticket
__device__ uint8_t g_gid8[262144];      // uint8 graph_id (fits L1)

#define XS 68
#define NODE_GRID 148
#define NPAIRS (NODE_GRID * 8)

#define MMA16816(c, a, b0, b1) \
    asm volatile("mma.sync.aligned.m16n8k16.row.col.f32.bf16.bf16.f32 " \
        "{%0,%1,%2,%3}, {%4,%5,%6,%7}, {%8,%9}, {%0,%1,%2,%3};" \
        : "+f"((c)[0]), "+f"((c)[1]), "+f"((c)[2]), "+f"((c)[3]) \
        : "r"((a)[0]), "r"((a)[1]), "r"((a)[2]), "r"((a)[3]), "r"(b0), "r"(b1))

#define PAIR_BAR(id) asm volatile("bar.sync %0, 64;" :: "r"(id) : "memory")

// truncation hi/lo split: hi = top-16 bits (exact bf16), lo = rn(x - hi)
__device__ __forceinline__ void tsplit2(float x0, float x1, uint32_t& hi, uint32_t& lo) {
    uint32_t u0 = __float_as_uint(x0), u1 = __float_as_uint(x1);
    hi = __byte_perm(u0, u1, 0x7632);
    float h0 = __uint_as_float(u0 & 0xFFFF0000u);
    float h1 = __uint_as_float(u1 & 0xFFFF0000u);
    float l0 = x0 - h0, l1 = x1 - h1;
    asm("cvt.rn.bf16x2.f32 %0, %1, %2;" : "=r"(lo) : "f"(l1), "f"(l0));
}

// ---------------------------------------------------------------------------
// Per-graph prep + gid8 conversion + queue reset. grid = B, block = 128.
// ---------------------------------------------------------------------------
__global__ void prep_kernel(const float* __restrict__ z,
                            const float* __restrict__ lp_w, const float* __restrict__ lp_b,
                            const float* __restrict__ nd1_w, const float* __restrict__ nd1_b,
                            const float* __restrict__ ed1_w,
                            const float* __restrict__ en1_w, const float* __restrict__ en1_b,
                            const float* __restrict__ en2_w, const float* __restrict__ en2_b,
                            const float* __restrict__ st1_w, const float* __restrict__ st1_b,
                            const float* __restrict__ st2_w, const float* __restrict__ st2_b,
                            const int* __restrict__ graph_id, int N,
                            float* __restrict__ out_energy, float* __restrict__ out_stress,
                            int B)
{
    const int b = blockIdx.x;
    const int t = threadIdx.x;
    __shared__ float zrow[32];
    __shared__ float zp[128];
    __shared__ float eh[64], sh[64];

    if (b == 0 && t == 0) g_ctr = NPAIRS;

    // gid8 conversion spread over all B blocks (coalesced byte stores)
    for (int i = b * 128 + t; i < N; i += B * 128)
        g_gid8[i] = (uint8_t)graph_id[i];

    if (t < 32) zrow[t] = z[b * 32 + t];
    __syncthreads();
    {
        float acc = lp_b[t];
        #pragma unroll
        for (int k = 0; k < 32; k++) acc = fmaf(zrow[k], lp_w[k * 128 + t], acc);
        zp[t] = fmaxf(acc, 0.f);
    }
    if (t < 64) {
        float a1 = en1_b[t], a2 = st1_b[t];
        #pragma unroll
        for (int k = 0; k < 32; k++) {
            float zv = zrow[k];
            a1 = fmaf(zv, en1_w[k * 64 + t], a1);
            a2 = fmaf(zv, st1_w[k * 64 + t], a2);
        }
        eh[t] = fmaxf(a1, 0.f);
        sh[t] = fmaxf(a2, 0.f);
    }
    __syncthreads();
    if (t < 64) {
        float as = 0.f, bd = 0.f, zb = nd1_b[t];
        #pragma unroll 4
        for (int k = 0; k < 128; k++) {
            float zv = zp[k];
            as = fmaf(zv, ed1_w[k * 64 + t], as);
            bd = fmaf(zv, ed1_w[(128 + k) * 64 + t], bd);
            zb = fmaf(zv, nd1_w[k * 64 + t], zb);
        }
        g_As[b * 64 + t] = as;
        g_Bd[b * 64 + t] = bd;
        g_zb[b * 64 + t] = zb;
    }
    if (t < 2) {
        float a = en2_b[t];
        #pragma unroll 8
        for (int k = 0; k < 64; k++) a = fmaf(eh[k], en2_w[k * 2 + t], a);
        out_energy[b * 2 + t] = a;
    }
    if (t >= 16 && t < 25) {
        int j = t - 16;
        float a = st2_b[j];
        #pragma unroll 8
        for (int k = 0; k < 64; k++) a = fmaf(sh[k], st2_w[k * 9 + j], a);
        out_stress[b * 9 + j] = a;
    }
}

// ---------------------------------------------------------------------------
// Edge table
// ---------------------------------------------------------------------------
__global__ void edge_table_kernel(const float* __restrict__ ed1_b,
                                  const float* __restrict__ ed2_w,
                                  const float* __restrict__ ed2_b)
{
    const int gs = blockIdx.x;
    const int gd = threadIdx.x;
    __shared__ float sAs[64], sb1[64], sw2[64 * 3], sb2[3];
    const int t = threadIdx.x;
    if (t < 64) { sAs[t] = g_As[gs * 64 + t]; sb1[t] = ed1_b[t]; }
    if (t >= 64 && t < 64 + 192) sw2[t - 64] = ed2_w[t - 64];
    if (t < 3) sb2[t] = ed2_b[t];
    __syncthreads();

    float o0 = sb2[0], o1 = sb2[1], o2 = sb2[2];
    const float4* bd4 = (const float4*)(&g_Bd[gd * 64]);
    #pragma unroll
    for (int k4 = 0; k4 < 16; k4++) {
        float4 bv = bd4[k4];
        int k = k4 * 4;
        float h;
        h = fmaxf(sAs[k + 0] + bv.x + sb1[k + 0], 0.f);
        o0 = fmaf(h, sw2[(k + 0) * 3 + 0], o0); o1 = fmaf(h, sw2[(k + 0) * 3 + 1], o1); o2 = fmaf(h, sw2[(k + 0) * 3 + 2], o2);
        h = fmaxf(sAs[k + 1] + bv.y + sb1[k + 1], 0.f);
        o0 = fmaf(h, sw2[(k + 1) * 3 + 0], o0); o1 = fmaf(h, sw2[(k + 1) * 3 + 1], o1); o2 = fmaf(h, sw2[(k + 1) * 3 + 2], o2);
        h = fmaxf(sAs[k + 2] + bv.z + sb1[k + 2], 0.f);
        o0 = fmaf(h, sw2[(k + 2) * 3 + 0], o0); o1 = fmaf(h, sw2[(k + 2) * 3 + 1], o1); o2 = fmaf(h, sw2[(k + 2) * 3 + 2], o2);
        h = fmaxf(sAs[k + 3] + bv.w + sb1[k + 3], 0.f);
        o0 = fmaf(h, sw2[(k + 3) * 3 + 0], o0); o1 = fmaf(h, sw2[(k + 3) * 3 + 1], o1); o2 = fmaf(h, sw2[(k + 3) * 3 + 2], o2);
    }
    g_table[gs * MAXB + gd] = make_float4(o0, o1, o2, 0.f);
}

// ---------------------------------------------------------------------------
// Persistent node kernel: 512 threads, 8 autonomous pairs, dynamic queue.
// Weights converted fp32 -> bf16 hi/lo IN-CTA during one-time staging.
// ---------------------------------------------------------------------------
#define NODE_SMEM_U32 (2*128*XS + 2*64*XS + 2*128*XS + 128 + 256 + 8)
#define NODE_SMEM_BYTES (NODE_SMEM_U32 * 4)

__global__ void __launch_bounds__(512, 1)
node_mma_kernel(const float* __restrict__ node_emb, const int* __restrict__ graph_id,
                const float* __restrict__ w1raw, const float* __restrict__ b1,
                const float* __restrict__ w2raw,
                const float* __restrict__ w3, const float* __restrict__ b3,
                float* __restrict__ out_node, int N, int U)
{
    extern __shared__ uint32_t su[];
    uint32_t* sW1h = su;                        // [128][XS]
    uint32_t* sW1l = sW1h + 128 * XS;
    uint32_t* sW2h = sW1l + 128 * XS;           // [64][XS]
    uint32_t* sW2l = sW2h + 64 * XS;
    uint32_t* sXh  = sW2l + 64 * XS;            // [128][XS]
    uint32_t* sXl  = sXh + 128 * XS;            // [128][XS]; merge aliases pair rows
    float*    sB1  = (float*)(sXl + 128 * XS);  // [128]
    float*    sW3  = sB1 + 128;                 // [64][4]
    int*      sNU  = (int*)(sW3 + 256);         // [8] next-unit per pair

    const int tid  = threadIdx.x;
    const int lane = tid & 31;
    const int w    = tid >> 5;       // 0..15
    const int p    = w >> 1;         // pair 0..7
    const int h    = w & 1;          // half
    const int g    = lane >> 2;
    const int tg   = lane & 3;
    const int r0   = p * 16;
    const int u    = tid & 63;       // thread within pair
    const int barid = p + 1;
    const int rloc = g + (h ? 8 : 0);           // local row this warp finalizes
    float* mrg = (float*)(sXl + p * 1088);      // 4KB inside own pair's sXl rows

    // ---- one-time staging: convert raw fp32 weights -> bf16 hi/lo smem ----
    for (int i = tid; i < 128 * 64; i += 512) {
        int n = i >> 6, kp = i & 63;
        float f0 = w1raw[(2 * kp) * 128 + n];       // W1^T[n][2kp]
        float f1 = w1raw[(2 * kp + 1) * 128 + n];
        uint32_t hi, lo;
        tsplit2(f0, f1, hi, lo);
        sW1h[n * XS + kp] = hi;
        sW1l[n * XS + kp] = lo;
    }
    for (int i = tid; i < 64 * 64; i += 512) {
        int n = i >> 6, kp = i & 63;
        float f0 = w2raw[(2 * kp) * 64 + n];        // W2^T[n][2kp]
        float f1 = w2raw[(2 * kp + 1) * 64 + n];
        uint32_t hi, lo;
        tsplit2(f0, f1, hi, lo);
        sW2h[n * XS + kp] = hi;
        sW2l[n * XS + kp] = lo;
    }
    if (tid < 128) sB1[tid] = b1[tid];
    else if (tid >= 256 && tid < 320) ((float4*)sW3)[tid - 256] = ((const float4*)w3)[tid - 256];
    const float b30 = b3[0], b31 = b3[1], b32 = b3[2], b33 = b3[3];

    // ---- prologue: stage this pair's first unit ----
    int unit = blockIdx.x * 8 + p;
    if (unit < U) {
        const int gbase = unit * 16;
        #pragma unroll
        for (int it = 0; it < 8; it++) {
            int idx = it * 64 + u;
            int rl  = idx >> 5;              // 0..15
            int q   = idx & 31;
            int gn  = gbase + rl;
            float4 v = (gn < N) ? ((const float4*)(node_emb + (size_t)gn * 128))[q]
                                : make_float4(0.f, 0.f, 0.f, 0.f);
            uint32_t h0v, l0v, h1v, l1v;
            tsplit2(v.x, v.y, h0v, l0v);
            tsplit2(v.z, v.w, h1v, l1v);
            *(uint2*)&sXh[(r0 + rl) * XS + 2 * q] = make_uint2(h0v, h1v);
            *(uint2*)&sXl[(r0 + rl) * XS + 2 * q] = make_uint2(l0v, l1v);
        }
    }
    __syncthreads();   // only block-wide sync

    while (unit < U) {
        const int gbase = unit * 16;
        const int grow = gbase + rloc;
        const int gid = graph_id[(grow < N) ? grow : (N - 1)];

        // grab next unit early; latency hidden under L1 MMAs
        if (h == 0 && lane == 0) sNU[p] = atomicAdd(&g_ctr, 1);

        // ---- Layer 1: 8 n-tiles (global nt = 8h+j), all 8 k-steps ----
        float acc[8][4];
        #pragma unroll
        for (int j = 0; j < 8; j++)
            #pragma unroll
            for (int q = 0; q < 4; q++) acc[j][q] = 0.f;

        const uint32_t* xh0 = &sXh[(r0 + g) * XS];
        const uint32_t* xh1 = &sXh[(r0 + g + 8) * XS];
        const uint32_t* xl0 = &sXl[(r0 + g) * XS];
        const uint32_t* xl1 = &sXl[(r0 + g + 8) * XS];

        #pragma unroll
        for (int s = 0; s < 8; s++) {
            const int o = s * 8 + tg;
            uint32_t aH[4] = { xh0[o], xh1[o], xh0[o + 4], xh1[o + 4] };
            uint32_t aL[4] = { xl0[o], xl1[o], xl0[o + 4], xl1[o + 4] };
            #pragma unroll
            for (int j = 0; j < 8; j++) {
                const int nrow = ((8 * h + j) * 8 + g) * XS;
                uint32_t bh0 = sW1h[nrow + o], bh1 = sW1h[nrow + o + 4];
                uint32_t bl0 = sW1l[nrow + o], bl1 = sW1l[nrow + o + 4];
                MMA16816(acc[j], aH, bh0, bh1);
                MMA16816(acc[j], aH, bl0, bl1);
                MMA16816(acc[j], aL, bh0, bh1);
            }
        }
        PAIR_BAR(barid);   // barA: pair done reading its sX rows; sNU visible

        // ---- prefetch next unit's X into registers ----
        const int  nunit = sNU[p];
        const bool nv    = nunit < U;
        float4 xp[8];
        if (nv) {
            const int nbase = nunit * 16;
            #pragma unroll
            for (int it = 0; it < 8; it++) {
                int idx = it * 64 + u;
                int gn  = nbase + (idx >> 5);
                xp[it] = (gn < N) ? ((const float4*)(node_emb + (size_t)gn * 128))[idx & 31]
                                  : make_float4(0.f, 0.f, 0.f, 0.f);
            }
        }

        // ---- epilogue 1 (registers): bias+relu, truncation split -> A2 ----
        uint32_t a2h[4][4], a2l[4][4];
        #pragma unroll
        for (int s2 = 0; s2 < 4; s2++) {
            int cA = (4 * h + s2) * 16 + tg * 2;
            int cB = cA + 8;
            float bA0 = sB1[cA], bA1 = sB1[cA + 1];
            float bB0 = sB1[cB], bB1 = sB1[cB + 1];
            tsplit2(fmaxf(acc[2 * s2][0] + bA0, 0.f),
                    fmaxf(acc[2 * s2][1] + bA1, 0.f), a2h[s2][0], a2l[s2][0]);
            tsplit2(fmaxf(acc[2 * s2][2] + bA0, 0.f),
                    fmaxf(acc[2 * s2][3] + bA1, 0.f), a2h[s2][1], a2l[s2][1]);
            tsplit2(fmaxf(acc[2 * s2 + 1][0] + bB0, 0.f),
                    fmaxf(acc[2 * s2 + 1][1] + bB1, 0.f), a2h[s2][2], a2l[s2][2]);
            tsplit2(fmaxf(acc[2 * s2 + 1][2] + bB0, 0.f),
                    fmaxf(acc[2 * s2 + 1][3] + bB1, 0.f), a2h[s2][3], a2l[s2][3]);
        }

        // ---- Layer 2: all 8 n-tiles, local k-half (4 steps) -> partial ----
        float acc2[8][4];
        #pragma unroll
        for (int j = 0; j < 8; j++)
            #pragma unroll
            for (int q = 0; q < 4; q++) acc2[j][q] = 0.f;

        #pragma unroll
        for (int s = 0; s < 4; s++) {
            const int o = (4 * h + s) * 8 + tg;
            #pragma unroll
            for (int j = 0; j < 8; j++) {
                const int nrow = (j * 8 + g) * XS;
                uint32_t bh0 = sW2h[nrow + o], bh1 = sW2h[nrow + o + 4];
                uint32_t bl0 = sW2l[nrow + o], bl1 = sW2l[nrow + o + 4];
                MMA16816(acc2[j], a2h[s], bh0, bh1);
                MMA16816(acc2[j], a2h[s], bl0, bl1);
                MMA16816(acc2[j], a2l[s], bh0, bh1);
            }
        }

        // ---- zb prefetch for this warp's row (L2 hit, hidden by merge) ----
        float2 zbv[8];
        {
            const float2* zp2 = (const float2*)(g_zb + gid * 64);
            #pragma unroll
            for (int nt = 0; nt < 8; nt++) zbv[nt] = zp2[nt * 4 + tg];
        }

        // ---- balanced merge: h0 stores rB-half, h1 stores rA-half ----
        {
            float* dstp = mrg + (h ? 512 : 0);
            int qo = h ? 0 : 2;
            #pragma unroll
            for (int j = 0; j < 8; j++) {
                dstp[(j * 2 + 0) * 32 + lane] = acc2[j][qo + 0];
                dstp[(j * 2 + 1) * 32 + lane] = acc2[j][qo + 1];
            }
        }
        PAIR_BAR(barid);   // barB

        // ---- each warp finalizes its own row ----
        {
            const float* srcp = mrg + (h ? 0 : 512);
            int qo = h ? 2 : 0;
            float o0 = 0.f, o1 = 0.f, o2 = 0.f, o3 = 0.f;
            #pragma unroll
            for (int nt = 0; nt < 8; nt++) {
                float v0 = acc2[nt][qo + 0] + srcp[(nt * 2 + 0) * 32 + lane];
                float v1 = acc2[nt][qo + 1] + srcp[(nt * 2 + 1) * 32 + lane];
                float hv0 = fmaxf(v0 + zbv[nt].x, 0.f);
                float hv1 = fmaxf(v1 + zbv[nt].y, 0.f);
                int c0 = nt * 8 + tg * 2;
                float4 w0 = *(const float4*)&sW3[c0 * 4];
                float4 w1 = *(const float4*)&sW3[(c0 + 1) * 4];
                o0 = fmaf(hv0, w0.x, fmaf(hv1, w1.x, o0));
                o1 = fmaf(hv0, w0.y, fmaf(hv1, w1.y, o1));
                o2 = fmaf(hv0, w0.z, fmaf(hv1, w1.z, o2));
                o3 = fmaf(hv0, w0.w, fmaf(hv1, w1.w, o3));
            }
            #pragma unroll
            for (int d = 1; d <= 2; d <<= 1) {
                o0 += __shfl_xor_sync(0xFFFFFFFF, o0, d);
                o1 += __shfl_xor_sync(0xFFFFFFFF, o1, d);
                o2 += __shfl_xor_sync(0xFFFFFFFF, o2, d);
                o3 += __shfl_xor_sync(0xFFFFFFFF, o3, d);
            }
            if (tg == 0 && grow < N)
                *(float4*)&out_node[(size_t)grow * 4] =
                    make_float4(o0 + b30, o1 + b31, o2 + b32, o3 + b33);
        }

        // ---- write next X hi (sXh dead since barA) ----
        if (nv) {
            #pragma unroll
            for (int it = 0; it < 8; it++) {
                int idx = it * 64 + u;
                int rl  = idx >> 5;
                int q   = idx & 31;
                float4 v = xp[it];
                uint32_t h0v, l0v, h1v, l1v;
                tsplit2(v.x, v.y, h0v, l0v);
                tsplit2(v.z, v.w, h1v, l1v);
                *(uint2*)&sXh[(r0 + rl) * XS + 2 * q] = make_uint2(h0v, h1v);
            }
        }
        PAIR_BAR(barid);   // barC: both warps' merge reads complete

        if (nv) {
            #pragma unroll
            for (int it = 0; it < 8; it++) {
                int idx = it * 64 + u;
                int rl  = idx >> 5;
                int q   = idx & 31;
                float4 v = xp[it];
                uint32_t h0v, l0v, h1v, l1v;
                tsplit2(v.x, v.y, h0v, l0v);
                tsplit2(v.z, v.w, h1v, l1v);
                *(uint2*)&sXl[(r0 + rl) * XS + 2 * q] = make_uint2(l0v, l1v);
            }
        }
        PAIR_BAR(barid);   // barD: staging done before next L1
        unit = nunit;
    }
}

// ---------------------------------------------------------------------------
// Edge gather: 4 edges/thread, uint8 gid (L1-resident after warmup)
// ---------------------------------------------------------------------------
__global__ void edge_gather_kernel(const int* __restrict__ src, const int* __restrict__ dst,
                                   float* __restrict__ out_edge, int E)
{
    int e = (blockIdx.x * blockDim.x + threadIdx.x) * 4;
    if (e >= E) return;
    if (e + 4 <= E) {
        int4 s = *(const int4*)(src + e);
        int4 d = *(const int4*)(dst + e);
        int gs0 = g_gid8[s.x], gs1 = g_gid8[s.y], gs2 = g_gid8[s.z], gs3 = g_gid8[s.w];
        int gd0 = g_gid8[d.x], gd1 = g_gid8[d.y], gd2 = g_gid8[d.z], gd3 = g_gid8[d.w];
        float4 t0 = g_table[gs0 * MAXB + gd0];
        float4 t1 = g_table[gs1 * MAXB + gd1];
        float4 t2 = g_table[gs2 * MAXB + gd2];
        float4 t3 = g_table[gs3 * MAXB + gd3];
        float* o = out_edge + (size_t)e * 3;
        ((float4*)o)[0] = make_float4(t0.x, t0.y, t0.z, t1.x);
        ((float4*)o)[1] = make_float4(t1.y, t1.z, t2.x, t2.y);
        ((float4*)o)[2] = make_float4(t2.z, t3.x, t3.y, t3.z);
    } else {
        for (int q = e; q < E; q++) {
            float4 t = g_table[g_gid8[src[q]] * MAXB + g_gid8[dst[q]]];
            out_edge[(size_t)q * 3 + 0] = t.x;
            out_edge[(size_t)q * 3 + 1] = t.y;
            out_edge[(size_t)q * 3 + 2] = t.z;
        }
    }
}

// ---------------------------------------------------------------------------
extern "C" void kernel_launch(void* const* d_in, const int* in_sizes, int n_in,
                              void* d_out, int out_size)
{
    const float* z        = (const float*)d_in[0];
    const float* node_emb = (const float*)d_in[1];
    const int*   graph_id = (const int*)  d_in[2];
    const int*   src      = (const int*)  d_in[3];
    const int*   dst      = (const int*)  d_in[4];
    const float* lp_w  = (const float*)d_in[5];
    const float* lp_b  = (const float*)d_in[6];
    const float* nep_w = (const float*)d_in[7];
    const float* nep_b = (const float*)d_in[8];
    const float* nd1_w = (const float*)d_in[9];
    const float* nd1_b = (const float*)d_in[10];
    const float* nd2_w = (const float*)d_in[11];
    const float* nd2_b = (const float*)d_in[12];
    const float* ed1_w = (const float*)d_in[13];
    const float* ed1_b = (const float*)d_in[14];
    const float* ed2_w = (const float*)d_in[15];
    const float* ed2_b = (const float*)d_in[16];
    const float* en1_w = (const float*)d_in[17];
    const float* en1_b = (const float*)d_in[18];
    const float* en2_w = (const float*)d_in[19];
    const float* en2_b = (const float*)d_in[20];
    const float* st1_w = (const float*)d_in[21];
    const float* st1_b = (const float*)d_in[22];
    const float* st2_w = (const float*)d_in[23];
    const float* st2_b = (const float*)d_in[24];

    const int B = in_sizes[0] / 32;
    const int N = in_sizes[1] / 128;
    const int E = in_sizes[3];

    float* out        = (float*)d_out;
    float* out_node   = out;
    float* out_edge   = out + (size_t)N * 4;
    float* out_energy = out + (size_t)N * 4 + (size_t)E * 3;
    float* out_stress = out_energy + (size_t)B * 2;

    cudaFuncSetAttribute(node_mma_kernel, cudaFuncAttributeMaxDynamicSharedMemorySize,
                         NODE_SMEM_BYTES);

    prep_kernel<<<B, 128>>>(z, lp_w, lp_b, nd1_w, nd1_b, ed1_w,
                            en1_w, en1_b, en2_w, en2_b,
                            st1_w, st1_b, st2_w, st2_b,
                            graph_id, N, out_energy, out_stress, B);

    edge_table_kernel<<<B, 256>>>(ed1_b, ed2_w, ed2_b);

    const int U = (N + 15) / 16;
    node_mma_kernel<<<NODE_GRID, 512, NODE_SMEM_BYTES>>>(node_emb, graph_id,
                                                         nep_w, nep_b, nd1_w,
                                                         nd2_w, nd2_b,
                                                         out_node, N, U);

    const int eth = (E + 3) / 4;
    edge_gather_kernel<<<(eth + 255) / 256, 256>>>(src, dst, out_edge, E);
}

// round 11
// speedup vs baseline: 1.0515x; 1.0278x over previous
#include <cuda_runtime.h>
#include <cuda_bf16.h>
#include <cstdint>

// ---------------------------------------------------------------------------
// CrystalDecoder on GB300 (sm_103a via compute_103 PTX -> HMMA mma.sync only)
// Node path: 16-warp pair-autonomous compensated mma.sync GEMM, dynamic queue,
//            in-CTA weight conversion (coalesced).
// Edge path: 256x256 lookup table + uint8-gid gather with L1/L2 cache split.
// ---------------------------------------------------------------------------

#define MAXB 256

__device__ float  g_zb[MAXB * 64];      // z_proj @ nd1_w + nd1_b
__device__ float  g_As[MAXB * 64];
__device__ float  g_Bd[MAXB * 64];
__device__ float4 g_table[MAXB * MAXB];
__device__ int    g_ctr;                // dynamic work-queue ticket
__device__ uint8_t g_gid8[262144];      // uint8 graph_id (fits L1)

#define XS 68
#define NODE_GRID 148
#define NPAIRS (NODE_GRID * 8)

#define MMA16816(c, a, b0, b1) \
    asm volatile("mma.sync.aligned.m16n8k16.row.col.f32.bf16.bf16.f32 " \
        "{%0,%1,%2,%3}, {%4,%5,%6,%7}, {%8,%9}, {%0,%1,%2,%3};" \
        : "+f"((c)[0]), "+f"((c)[1]), "+f"((c)[2]), "+f"((c)[3]) \
        : "r"((a)[0]), "r"((a)[1]), "r"((a)[2]), "r"((a)[3]), "r"(b0), "r"(b1))

#define PAIR_BAR(id) asm volatile("bar.sync %0, 64;" :: "r"(id) : "memory")

// truncation hi/lo split: hi = top-16 bits (exact bf16), lo = rn(x - hi)
__device__ __forceinline__ void tsplit2(float x0, float x1, uint32_t& hi, uint32_t& lo) {
    uint32_t u0 = __float_as_uint(x0), u1 = __float_as_uint(x1);
    hi = __byte_perm(u0, u1, 0x7632);
    float h0 = __uint_as_float(u0 & 0xFFFF0000u);
    float h1 = __uint_as_float(u1 & 0xFFFF0000u);
    float l0 = x0 - h0, l1 = x1 - h1;
    asm("cvt.rn.bf16x2.f32 %0, %1, %2;" : "=r"(lo) : "f"(l1), "f"(l0));
}

// ---------------------------------------------------------------------------
// Per-graph prep (256 threads, k-split GEMV) + gid8 + queue reset. grid = B.
// ---------------------------------------------------------------------------
__global__ void __launch_bounds__(256)
prep_kernel(const float* __restrict__ z,
            const float* __restrict__ lp_w, const float* __restrict__ lp_b,
            const float* __restrict__ nd1_w, const float* __restrict__ nd1_b,
            const float* __restrict__ ed1_w,
            const float* __restrict__ en1_w, const float* __restrict__ en1_b,
            const float* __restrict__ en2_w, const float* __restrict__ en2_b,
            const float* __restrict__ st1_w, const float* __restrict__ st1_b,
            const float* __restrict__ st2_w, const float* __restrict__ st2_b,
            const int* __restrict__ graph_id, int N,
            float* __restrict__ out_energy, float* __restrict__ out_stress,
            int B)
{
    const int b = blockIdx.x;
    const int t = threadIdx.x;
    __shared__ float zrow[32];
    __shared__ float zp[128];
    __shared__ float eh[64], sh[64];

    if (b == 0 && t == 0) g_ctr = NPAIRS;

    // gid8 conversion spread over all B blocks (coalesced byte stores)
    for (int i = b * 256 + t; i < N; i += B * 256)
        g_gid8[i] = (uint8_t)graph_id[i];

    if (t < 32) zrow[t] = z[b * 32 + t];
    __syncthreads();
    if (t < 128) {
        float acc = lp_b[t];
        #pragma unroll
        for (int k = 0; k < 32; k++) acc = fmaf(zrow[k], lp_w[k * 128 + t], acc);
        zp[t] = fmaxf(acc, 0.f);
    } else if (t < 192) {
        int o = t - 128;
        float a1 = en1_b[o], a2 = st1_b[o];
        #pragma unroll
        for (int k = 0; k < 32; k++) {
            float zv = zrow[k];
            a1 = fmaf(zv, en1_w[k * 64 + o], a1);
            a2 = fmaf(zv, st1_w[k * 64 + o], a2);
        }
        eh[o] = fmaxf(a1, 0.f);
        sh[o] = fmaxf(a2, 0.f);
    }
    __syncthreads();

    // heavy GEMV: 64 outputs x 4 k-quarters; t = o*4 + q
    {
        const int o = t >> 2;       // 0..63
        const int q = t & 3;        // k quarter
        const int k0 = q * 32;
        float as = 0.f, bd = 0.f, zb = (q == 0) ? nd1_b[o] : 0.f;
        #pragma unroll 8
        for (int ki = 0; ki < 32; ki++) {
            int k = k0 + ki;
            float zv = zp[k];
            as = fmaf(zv, ed1_w[k * 64 + o], as);
            bd = fmaf(zv, ed1_w[(128 + k) * 64 + o], bd);
            zb = fmaf(zv, nd1_w[k * 64 + o], zb);
        }
        #pragma unroll
        for (int d = 1; d <= 2; d <<= 1) {
            as += __shfl_xor_sync(0xFFFFFFFF, as, d);
            bd += __shfl_xor_sync(0xFFFFFFFF, bd, d);
            zb += __shfl_xor_sync(0xFFFFFFFF, zb, d);
        }
        if (q == 0) {
            g_As[b * 64 + o] = as;
            g_Bd[b * 64 + o] = bd;
            g_zb[b * 64 + o] = zb;
        }
    }

    if (t < 2) {
        float a = en2_b[t];
        #pragma unroll 8
        for (int k = 0; k < 64; k++) a = fmaf(eh[k], en2_w[k * 2 + t], a);
        out_energy[b * 2 + t] = a;
    }
    if (t >= 16 && t < 25) {
        int j = t - 16;
        float a = st2_b[j];
        #pragma unroll 8
        for (int k = 0; k < 64; k++) a = fmaf(sh[k], st2_w[k * 9 + j], a);
        out_stress[b * 9 + j] = a;
    }
}

// ---------------------------------------------------------------------------
// Edge table
// ---------------------------------------------------------------------------
__global__ void edge_table_kernel(const float* __restrict__ ed1_b,
                                  const float* __restrict__ ed2_w,
                                  const float* __restrict__ ed2_b)
{
    const int gs = blockIdx.x;
    const int gd = threadIdx.x;
    __shared__ float sAs[64], sb1[64], sw2[64 * 3], sb2[3];
    const int t = threadIdx.x;
    if (t < 64) { sAs[t] = g_As[gs * 64 + t]; sb1[t] = ed1_b[t]; }
    if (t >= 64 && t < 64 + 192) sw2[t - 64] = ed2_w[t - 64];
    if (t < 3) sb2[t] = ed2_b[t];
    __syncthreads();

    float o0 = sb2[0], o1 = sb2[1], o2 = sb2[2];
    const float4* bd4 = (const float4*)(&g_Bd[gd * 64]);
    #pragma unroll
    for (int k4 = 0; k4 < 16; k4++) {
        float4 bv = bd4[k4];
        int k = k4 * 4;
        float h;
        h = fmaxf(sAs[k + 0] + bv.x + sb1[k + 0], 0.f);
        o0 = fmaf(h, sw2[(k + 0) * 3 + 0], o0); o1 = fmaf(h, sw2[(k + 0) * 3 + 1], o1); o2 = fmaf(h, sw2[(k + 0) * 3 + 2], o2);
        h = fmaxf(sAs[k + 1] + bv.y + sb1[k + 1], 0.f);
        o0 = fmaf(h, sw2[(k + 1) * 3 + 0], o0); o1 = fmaf(h, sw2[(k + 1) * 3 + 1], o1); o2 = fmaf(h, sw2[(k + 1) * 3 + 2], o2);
        h = fmaxf(sAs[k + 2] + bv.z + sb1[k + 2], 0.f);
        o0 = fmaf(h, sw2[(k + 2) * 3 + 0], o0); o1 = fmaf(h, sw2[(k + 2) * 3 + 1], o1); o2 = fmaf(h, sw2[(k + 2) * 3 + 2], o2);
        h = fmaxf(sAs[k + 3] + bv.w + sb1[k + 3], 0.f);
        o0 = fmaf(h, sw2[(k + 3) * 3 + 0], o0); o1 = fmaf(h, sw2[(k + 3) * 3 + 1], o1); o2 = fmaf(h, sw2[(k + 3) * 3 + 2], o2);
    }
    g_table[gs * MAXB + gd] = make_float4(o0, o1, o2, 0.f);
}

// ---------------------------------------------------------------------------
// Persistent node kernel: 512 threads, 8 autonomous pairs, dynamic queue.
// Weights converted fp32 -> bf16 hi/lo IN-CTA (coalesced reads).
// ---------------------------------------------------------------------------
#define NODE_SMEM_U32 (2*128*XS + 2*64*XS + 2*128*XS + 128 + 256 + 8)
#define NODE_SMEM_BYTES (NODE_SMEM_U32 * 4)

__global__ void __launch_bounds__(512, 1)
node_mma_kernel(const float* __restrict__ node_emb, const int* __restrict__ graph_id,
                const float* __restrict__ w1raw, const float* __restrict__ b1,
                const float* __restrict__ w2raw,
                const float* __restrict__ w3, const float* __restrict__ b3,
                float* __restrict__ out_node, int N, int U)
{
    extern __shared__ uint32_t su[];
    uint32_t* sW1h = su;                        // [128][XS]
    uint32_t* sW1l = sW1h + 128 * XS;
    uint32_t* sW2h = sW1l + 128 * XS;           // [64][XS]
    uint32_t* sW2l = sW2h + 64 * XS;
    uint32_t* sXh  = sW2l + 64 * XS;            // [128][XS]
    uint32_t* sXl  = sXh + 128 * XS;            // [128][XS]; merge aliases pair rows
    float*    sB1  = (float*)(sXl + 128 * XS);  // [128]
    float*    sW3  = sB1 + 128;                 // [64][4]
    int*      sNU  = (int*)(sW3 + 256);         // [8] next-unit per pair

    const int tid  = threadIdx.x;
    const int lane = tid & 31;
    const int w    = tid >> 5;       // 0..15
    const int p    = w >> 1;         // pair 0..7
    const int h    = w & 1;          // half
    const int g    = lane >> 2;
    const int tg   = lane & 3;
    const int r0   = p * 16;
    const int u    = tid & 63;       // thread within pair
    const int barid = p + 1;
    const int rloc = g + (h ? 8 : 0);           // local row this warp finalizes
    float* mrg = (float*)(sXl + p * 1088);      // 4KB inside own pair's sXl rows

    // ---- one-time staging: convert fp32 weights -> bf16 hi/lo (coalesced) ----
    for (int i = tid; i < 128 * 64; i += 512) {
        int kp = i >> 7, n = i & 127;               // consecutive tid -> consecutive n
        float f0 = w1raw[(2 * kp) * 128 + n];       // W1^T[n][2kp], coalesced
        float f1 = w1raw[(2 * kp + 1) * 128 + n];
        uint32_t hi, lo;
        tsplit2(f0, f1, hi, lo);
        sW1h[n * XS + kp] = hi;
        sW1l[n * XS + kp] = lo;
    }
    for (int i = tid; i < 64 * 64; i += 512) {
        int kp = i >> 6, n = i & 63;
        float f0 = w2raw[(2 * kp) * 64 + n];        // coalesced
        float f1 = w2raw[(2 * kp + 1) * 64 + n];
        uint32_t hi, lo;
        tsplit2(f0, f1, hi, lo);
        sW2h[n * XS + kp] = hi;
        sW2l[n * XS + kp] = lo;
    }
    if (tid < 128) sB1[tid] = b1[tid];
    else if (tid >= 256 && tid < 320) ((float4*)sW3)[tid - 256] = ((const float4*)w3)[tid - 256];
    const float b30 = b3[0], b31 = b3[1], b32 = b3[2], b33 = b3[3];

    // ---- prologue: stage this pair's first unit ----
    int unit = blockIdx.x * 8 + p;
    if (unit < U) {
        const int gbase = unit * 16;
        #pragma unroll
        for (int it = 0; it < 8; it++) {
            int idx = it * 64 + u;
            int rl  = idx >> 5;              // 0..15
            int q   = idx & 31;
            int gn  = gbase + rl;
            float4 v = (gn < N) ? ((const float4*)(node_emb + (size_t)gn * 128))[q]
                                : make_float4(0.f, 0.f, 0.f, 0.f);
            uint32_t h0v, l0v, h1v, l1v;
            tsplit2(v.x, v.y, h0v, l0v);
            tsplit2(v.z, v.w, h1v, l1v);
            *(uint2*)&sXh[(r0 + rl) * XS + 2 * q] = make_uint2(h0v, h1v);
            *(uint2*)&sXl[(r0 + rl) * XS + 2 * q] = make_uint2(l0v, l1v);
        }
    }
    __syncthreads();   // only block-wide sync

    while (unit < U) {
        const int gbase = unit * 16;
        const int grow = gbase + rloc;
        const int gid = graph_id[(grow < N) ? grow : (N - 1)];

        // grab next unit early; latency hidden under L1 MMAs
        if (h == 0 && lane == 0) sNU[p] = atomicAdd(&g_ctr, 1);

        // ---- Layer 1: 8 n-tiles (global nt = 8h+j), all 8 k-steps ----
        float acc[8][4];
        #pragma unroll
        for (int j = 0; j < 8; j++)
            #pragma unroll
            for (int q = 0; q < 4; q++) acc[j][q] = 0.f;

        const uint32_t* xh0 = &sXh[(r0 + g) * XS];
        const uint32_t* xh1 = &sXh[(r0 + g + 8) * XS];
        const uint32_t* xl0 = &sXl[(r0 + g) * XS];
        const uint32_t* xl1 = &sXl[(r0 + g + 8) * XS];

        #pragma unroll
        for (int s = 0; s < 8; s++) {
            const int o = s * 8 + tg;
            uint32_t aH[4] = { xh0[o], xh1[o], xh0[o + 4], xh1[o + 4] };
            uint32_t aL[4] = { xl0[o], xl1[o], xl0[o + 4], xl1[o + 4] };
            #pragma unroll
            for (int j = 0; j < 8; j++) {
                const int nrow = ((8 * h + j) * 8 + g) * XS;
                uint32_t bh0 = sW1h[nrow + o], bh1 = sW1h[nrow + o + 4];
                uint32_t bl0 = sW1l[nrow + o], bl1 = sW1l[nrow + o + 4];
                MMA16816(acc[j], aH, bh0, bh1);
                MMA16816(acc[j], aH, bl0, bl1);
                MMA16816(acc[j], aL, bh0, bh1);
            }
        }
        PAIR_BAR(barid);   // barA: pair done reading its sX rows; sNU visible

        // ---- prefetch next unit's X into registers ----
        const int  nunit = sNU[p];
        const bool nv    = nunit < U;
        float4 xp[8];
        if (nv) {
            const int nbase = nunit * 16;
            #pragma unroll
            for (int it = 0; it < 8; it++) {
                int idx = it * 64 + u;
                int gn  = nbase + (idx >> 5);
                xp[it] = (gn < N) ? ((const float4*)(node_emb + (size_t)gn * 128))[idx & 31]
                                  : make_float4(0.f, 0.f, 0.f, 0.f);
            }
        }

        // ---- epilogue 1 (registers): bias+relu, truncation split -> A2 ----
        uint32_t a2h[4][4], a2l[4][4];
        #pragma unroll
        for (int s2 = 0; s2 < 4; s2++) {
            int cA = (4 * h + s2) * 16 + tg * 2;
            int cB = cA + 8;
            float bA0 = sB1[cA], bA1 = sB1[cA + 1];
            float bB0 = sB1[cB], bB1 = sB1[cB + 1];
            tsplit2(fmaxf(acc[2 * s2][0] + bA0, 0.f),
                    fmaxf(acc[2 * s2][1] + bA1, 0.f), a2h[s2][0], a2l[s2][0]);
            tsplit2(fmaxf(acc[2 * s2][2] + bA0, 0.f),
                    fmaxf(acc[2 * s2][3] + bA1, 0.f), a2h[s2][1], a2l[s2][1]);
            tsplit2(fmaxf(acc[2 * s2 + 1][0] + bB0, 0.f),
                    fmaxf(acc[2 * s2 + 1][1] + bB1, 0.f), a2h[s2][2], a2l[s2][2]);
            tsplit2(fmaxf(acc[2 * s2 + 1][2] + bB0, 0.f),
                    fmaxf(acc[2 * s2 + 1][3] + bB1, 0.f), a2h[s2][3], a2l[s2][3]);
        }

        // ---- Layer 2: all 8 n-tiles, local k-half (4 steps) -> partial ----
        float acc2[8][4];
        #pragma unroll
        for (int j = 0; j < 8; j++)
            #pragma unroll
            for (int q = 0; q < 4; q++) acc2[j][q] = 0.f;

        #pragma unroll
        for (int s = 0; s < 4; s++) {
            const int o = (4 * h + s) * 8 + tg;
            #pragma unroll
            for (int j = 0; j < 8; j++) {
                const int nrow = (j * 8 + g) * XS;
                uint32_t bh0 = sW2h[nrow + o], bh1 = sW2h[nrow + o + 4];
                uint32_t bl0 = sW2l[nrow + o], bl1 = sW2l[nrow + o + 4];
                MMA16816(acc2[j], a2h[s], bh0, bh1);
                MMA16816(acc2[j], a2h[s], bl0, bl1);
                MMA16816(acc2[j], a2l[s], bh0, bh1);
            }
        }

        // ---- zb prefetch for this warp's row (L2 hit, hidden by merge) ----
        float2 zbv[8];
        {
            const float2* zp2 = (const float2*)(g_zb + gid * 64);
            #pragma unroll
            for (int nt = 0; nt < 8; nt++) zbv[nt] = zp2[nt * 4 + tg];
        }

        // ---- balanced merge: h0 stores rB-half, h1 stores rA-half ----
        {
            float* dstp = mrg + (h ? 512 : 0);
            int qo = h ? 0 : 2;
            #pragma unroll
            for (int j = 0; j < 8; j++) {
                dstp[(j * 2 + 0) * 32 + lane] = acc2[j][qo + 0];
                dstp[(j * 2 + 1) * 32 + lane] = acc2[j][qo + 1];
            }
        }
        PAIR_BAR(barid);   // barB

        // ---- each warp finalizes its own row ----
        {
            const float* srcp = mrg + (h ? 0 : 512);
            int qo = h ? 2 : 0;
            float o0 = 0.f, o1 = 0.f, o2 = 0.f, o3 = 0.f;
            #pragma unroll
            for (int nt = 0; nt < 8; nt++) {
                float v0 = acc2[nt][qo + 0] + srcp[(nt * 2 + 0) * 32 + lane];
                float v1 = acc2[nt][qo + 1] + srcp[(nt * 2 + 1) * 32 + lane];
                float hv0 = fmaxf(v0 + zbv[nt].x, 0.f);
                float hv1 = fmaxf(v1 + zbv[nt].y, 0.f);
                int c0 = nt * 8 + tg * 2;
                float4 w0 = *(const float4*)&sW3[c0 * 4];
                float4 w1 = *(const float4*)&sW3[(c0 + 1) * 4];
                o0 = fmaf(hv0, w0.x, fmaf(hv1, w1.x, o0));
                o1 = fmaf(hv0, w0.y, fmaf(hv1, w1.y, o1));
                o2 = fmaf(hv0, w0.z, fmaf(hv1, w1.z, o2));
                o3 = fmaf(hv0, w0.w, fmaf(hv1, w1.w, o3));
            }
            #pragma unroll
            for (int d = 1; d <= 2; d <<= 1) {
                o0 += __shfl_xor_sync(0xFFFFFFFF, o0, d);
                o1 += __shfl_xor_sync(0xFFFFFFFF, o1, d);
                o2 += __shfl_xor_sync(0xFFFFFFFF, o2, d);
                o3 += __shfl_xor_sync(0xFFFFFFFF, o3, d);
            }
            if (tg == 0 && grow < N)
                *(float4*)&out_node[(size_t)grow * 4] =
                    make_float4(o0 + b30, o1 + b31, o2 + b32, o3 + b33);
        }

        // ---- write next X hi (sXh dead since barA) ----
        if (nv) {
            #pragma unroll
            for (int it = 0; it < 8; it++) {
                int idx = it * 64 + u;
                int rl  = idx >> 5;
                int q   = idx & 31;
                float4 v = xp[it];
                uint32_t h0v, l0v, h1v, l1v;
                tsplit2(v.x, v.y, h0v, l0v);
                tsplit2(v.z, v.w, h1v, l1v);
                *(uint2*)&sXh[(r0 + rl) * XS + 2 * q] = make_uint2(h0v, h1v);
            }
        }
        PAIR_BAR(barid);   // barC: both warps' merge reads complete

        if (nv) {
            #pragma unroll
            for (int it = 0; it < 8; it++) {
                int idx = it * 64 + u;
                int rl  = idx >> 5;
                int q   = idx & 31;
                float4 v = xp[it];
                uint32_t h0v, l0v, h1v, l1v;
                tsplit2(v.x, v.y, h0v, l0v);
                tsplit2(v.z, v.w, h1v, l1v);
                *(uint2*)&sXl[(r0 + rl) * XS + 2 * q] = make_uint2(l0v, l1v);
            }
        }
        PAIR_BAR(barid);   // barD: staging done before next L1
        unit = nunit;
    }
}

// ---------------------------------------------------------------------------
// Edge gather: 4 edges/thread. gid8 L1-cached; table L2-only (.cg);
// src/dst + stores streaming (.cs) to preserve L1 for gid8.
// ---------------------------------------------------------------------------
__global__ void edge_gather_kernel(const int* __restrict__ src, const int* __restrict__ dst,
                                   float* __restrict__ out_edge, int E)
{
    int e = (blockIdx.x * blockDim.x + threadIdx.x) * 4;
    if (e >= E) return;
    if (e + 4 <= E) {
        int4 s = __ldcs((const int4*)(src + e));
        int4 d = __ldcs((const int4*)(dst + e));
        int gs0 = g_gid8[s.x], gs1 = g_gid8[s.y], gs2 = g_gid8[s.z], gs3 = g_gid8[s.w];
        int gd0 = g_gid8[d.x], gd1 = g_gid8[d.y], gd2 = g_gid8[d.z], gd3 = g_gid8[d.w];
        float4 t0 = __ldcg(&g_table[gs0 * MAXB + gd0]);
        float4 t1 = __ldcg(&g_table[gs1 * MAXB + gd1]);
        float4 t2 = __ldcg(&g_table[gs2 * MAXB + gd2]);
        float4 t3 = __ldcg(&g_table[gs3 * MAXB + gd3]);
        float* o = out_edge + (size_t)e * 3;
        __stcs((float4*)o,     make_float4(t0.x, t0.y, t0.z, t1.x));
        __stcs((float4*)o + 1, make_float4(t1.y, t1.z, t2.x, t2.y));
        __stcs((float4*)o + 2, make_float4(t2.z, t3.x, t3.y, t3.z));
    } else {
        for (int q = e; q < E; q++) {
            float4 t = __ldcg(&g_table[g_gid8[src[q]] * MAXB + g_gid8[dst[q]]]);
            out_edge[(size_t)q * 3 + 0] = t.x;
            out_edge[(size_t)q * 3 + 1] = t.y;
            out_edge[(size_t)q * 3 + 2] = t.z;
        }
    }
}

// ---------------------------------------------------------------------------
extern "C" void kernel_launch(void* const* d_in, const int* in_sizes, int n_in,
                              void* d_out, int out_size)
{
    const float* z        = (const float*)d_in[0];
    const float* node_emb = (const float*)d_in[1];
    const int*   graph_id = (const int*)  d_in[2];
    const int*   src      = (const int*)  d_in[3];
    const int*   dst      = (const int*)  d_in[4];
    const float* lp_w  = (const float*)d_in[5];
    const float* lp_b  = (const float*)d_in[6];
    const float* nep_w = (const float*)d_in[7];
    const float* nep_b = (const float*)d_in[8];
    const float* nd1_w = (const float*)d_in[9];
    const float* nd1_b = (const float*)d_in[10];
    const float* nd2_w = (const float*)d_in[11];
    const float* nd2_b = (const float*)d_in[12];
    const float* ed1_w = (const float*)d_in[13];
    const float* ed1_b = (const float*)d_in[14];
    const float* ed2_w = (const float*)d_in[15];
    const float* ed2_b = (const float*)d_in[16];
    const float* en1_w = (const float*)d_in[17];
    const float* en1_b = (const float*)d_in[18];
    const float* en2_w = (const float*)d_in[19];
    const float* en2_b = (const float*)d_in[20];
    const float* st1_w = (const float*)d_in[21];
    const float* st1_b = (const float*)d_in[22];
    const float* st2_w = (const float*)d_in[23];
    const float* st2_b = (const float*)d_in[24];

    const int B = in_sizes[0] / 32;
    const int N = in_sizes[1] / 128;
    const int E = in_sizes[3];

    float* out        = (float*)d_out;
    float* out_node   = out;
    float* out_edge   = out + (size_t)N * 4;
    float* out_energy = out + (size_t)N * 4 + (size_t)E * 3;
    float* out_stress = out_energy + (size_t)B * 2;

    cudaFuncSetAttribute(node_mma_kernel, cudaFuncAttributeMaxDynamicSharedMemorySize,
                         NODE_SMEM_BYTES);

    prep_kernel<<<B, 256>>>(z, lp_w, lp_b, nd1_w, nd1_b, ed1_w,
                            en1_w, en1_b, en2_w, en2_b,
                            st1_w, st1_b, st2_w, st2_b,
                            graph_id, N, out_energy, out_stress, B);

    edge_table_kernel<<<B, 256>>>(ed1_b, ed2_w, ed2_b);

    const int U = (N + 15) / 16;
    node_mma_kernel<<<NODE_GRID, 512, NODE_SMEM_BYTES>>>(node_emb, graph_id,
                                                         nep_w, nep_b, nd1_w,
                                                         nd2_w, nd2_b,
                                                         out_node, N, U);

    const int eth = (E + 3) / 4;
    edge_gather_kernel<<<(eth + 255) / 256, 256>>>(src, dst, out_edge, E);
}

// round 12
// speedup vs baseline: 1.2234x; 1.1634x over previous
#include <cuda_runtime.h>
#include <cuda_bf16.h>
#include <cuda_fp16.h>
#include <cstdint>

// ---------------------------------------------------------------------------
// CrystalDecoder on GB300 (sm_103a via compute_103 PTX -> HMMA mma.sync only)
// Node path: 16-warp pair-autonomous fp16 mma.sync GEMM with 2-term
//            weight-only compensation (W = Whi + Wlo, X single fp16).
// Edge path: 256x256 lookup table + uint8-gid gather with cache-policy split.
// ---------------------------------------------------------------------------

#define MAXB 256

__device__ float  g_zb[MAXB * 64];      // z_proj @ nd1_w + nd1_b
__device__ float  g_As[MAXB * 64];
__device__ float  g_Bd[MAXB * 64];
__device__ float4 g_table[MAXB * MAXB];
__device__ int    g_ctr;                // dynamic work-queue ticket
__device__ uint8_t g_gid8[262144];      // uint8 graph_id (fits L1)

#define XS 68
#define NODE_GRID 148
#define NPAIRS (NODE_GRID * 8)

#define MMAF16(c, a, b0, b1) \
    asm volatile("mma.sync.aligned.m16n8k16.row.col.f32.f16.f16.f32 " \
        "{%0,%1,%2,%3}, {%4,%5,%6,%7}, {%8,%9}, {%0,%1,%2,%3};" \
        : "+f"((c)[0]), "+f"((c)[1]), "+f"((c)[2]), "+f"((c)[3]) \
        : "r"((a)[0]), "r"((a)[1]), "r"((a)[2]), "r"((a)[3]), "r"(b0), "r"(b1))

#define PAIR_BAR(id) asm volatile("bar.sync %0, 64;" :: "r"(id) : "memory")

__device__ __forceinline__ uint32_t pkh2(float a, float b) {
    __half2 t = __floats2half2_rn(a, b);
    return *(uint32_t*)&t;
}

// ---------------------------------------------------------------------------
// Per-graph prep (256 threads, k-split GEMV) + gid8 + queue reset. grid = B.
// ---------------------------------------------------------------------------
__global__ void __launch_bounds__(256)
prep_kernel(const float* __restrict__ z,
            const float* __restrict__ lp_w, const float* __restrict__ lp_b,
            const float* __restrict__ nd1_w, const float* __restrict__ nd1_b,
            const float* __restrict__ ed1_w,
            const float* __restrict__ en1_w, const float* __restrict__ en1_b,
            const float* __restrict__ en2_w, const float* __restrict__ en2_b,
            const float* __restrict__ st1_w, const float* __restrict__ st1_b,
            const float* __restrict__ st2_w, const float* __restrict__ st2_b,
            const int* __restrict__ graph_id, int N,
            float* __restrict__ out_energy, float* __restrict__ out_stress,
            int B)
{
    const int b = blockIdx.x;
    const int t = threadIdx.x;
    __shared__ float zrow[32];
    __shared__ float zp[128];
    __shared__ float eh[64], sh[64];

    if (b == 0 && t == 0) g_ctr = NPAIRS;

    for (int i = b * 256 + t; i < N; i += B * 256)
        g_gid8[i] = (uint8_t)graph_id[i];

    if (t < 32) zrow[t] = z[b * 32 + t];
    __syncthreads();
    if (t < 128) {
        float acc = lp_b[t];
        #pragma unroll
        for (int k = 0; k < 32; k++) acc = fmaf(zrow[k], lp_w[k * 128 + t], acc);
        zp[t] = fmaxf(acc, 0.f);
    } else if (t < 192) {
        int o = t - 128;
        float a1 = en1_b[o], a2 = st1_b[o];
        #pragma unroll
        for (int k = 0; k < 32; k++) {
            float zv = zrow[k];
            a1 = fmaf(zv, en1_w[k * 64 + o], a1);
            a2 = fmaf(zv, st1_w[k * 64 + o], a2);
        }
        eh[o] = fmaxf(a1, 0.f);
        sh[o] = fmaxf(a2, 0.f);
    }
    __syncthreads();

    {
        const int o = t >> 2;
        const int q = t & 3;
        const int k0 = q * 32;
        float as = 0.f, bd = 0.f, zb = (q == 0) ? nd1_b[o] : 0.f;
        #pragma unroll 8
        for (int ki = 0; ki < 32; ki++) {
            int k = k0 + ki;
            float zv = zp[k];
            as = fmaf(zv, ed1_w[k * 64 + o], as);
            bd = fmaf(zv, ed1_w[(128 + k) * 64 + o], bd);
            zb = fmaf(zv, nd1_w[k * 64 + o], zb);
        }
        #pragma unroll
        for (int d = 1; d <= 2; d <<= 1) {
            as += __shfl_xor_sync(0xFFFFFFFF, as, d);
            bd += __shfl_xor_sync(0xFFFFFFFF, bd, d);
            zb += __shfl_xor_sync(0xFFFFFFFF, zb, d);
        }
        if (q == 0) {
            g_As[b * 64 + o] = as;
            g_Bd[b * 64 + o] = bd;
            g_zb[b * 64 + o] = zb;
        }
    }

    if (t < 2) {
        float a = en2_b[t];
        #pragma unroll 8
        for (int k = 0; k < 64; k++) a = fmaf(eh[k], en2_w[k * 2 + t], a);
        out_energy[b * 2 + t] = a;
    }
    if (t >= 16 && t < 25) {
        int j = t - 16;
        float a = st2_b[j];
        #pragma unroll 8
        for (int k = 0; k < 64; k++) a = fmaf(sh[k], st2_w[k * 9 + j], a);
        out_stress[b * 9 + j] = a;
    }
}

// ---------------------------------------------------------------------------
// Edge table
// ---------------------------------------------------------------------------
__global__ void edge_table_kernel(const float* __restrict__ ed1_b,
                                  const float* __restrict__ ed2_w,
                                  const float* __restrict__ ed2_b)
{
    const int gs = blockIdx.x;
    const int gd = threadIdx.x;
    __shared__ float sAs[64], sb1[64], sw2[64 * 3], sb2[3];
    const int t = threadIdx.x;
    if (t < 64) { sAs[t] = g_As[gs * 64 + t]; sb1[t] = ed1_b[t]; }
    if (t >= 64 && t < 64 + 192) sw2[t - 64] = ed2_w[t - 64];
    if (t < 3) sb2[t] = ed2_b[t];
    __syncthreads();

    float o0 = sb2[0], o1 = sb2[1], o2 = sb2[2];
    const float4* bd4 = (const float4*)(&g_Bd[gd * 64]);
    #pragma unroll
    for (int k4 = 0; k4 < 16; k4++) {
        float4 bv = bd4[k4];
        int k = k4 * 4;
        float h;
        h = fmaxf(sAs[k + 0] + bv.x + sb1[k + 0], 0.f);
        o0 = fmaf(h, sw2[(k + 0) * 3 + 0], o0); o1 = fmaf(h, sw2[(k + 0) * 3 + 1], o1); o2 = fmaf(h, sw2[(k + 0) * 3 + 2], o2);
        h = fmaxf(sAs[k + 1] + bv.y + sb1[k + 1], 0.f);
        o0 = fmaf(h, sw2[(k + 1) * 3 + 0], o0); o1 = fmaf(h, sw2[(k + 1) * 3 + 1], o1); o2 = fmaf(h, sw2[(k + 1) * 3 + 2], o2);
        h = fmaxf(sAs[k + 2] + bv.z + sb1[k + 2], 0.f);
        o0 = fmaf(h, sw2[(k + 2) * 3 + 0], o0); o1 = fmaf(h, sw2[(k + 2) * 3 + 1], o1); o2 = fmaf(h, sw2[(k + 2) * 3 + 2], o2);
        h = fmaxf(sAs[k + 3] + bv.w + sb1[k + 3], 0.f);
        o0 = fmaf(h, sw2[(k + 3) * 3 + 0], o0); o1 = fmaf(h, sw2[(k + 3) * 3 + 1], o1); o2 = fmaf(h, sw2[(k + 3) * 3 + 2], o2);
    }
    g_table[gs * MAXB + gd] = make_float4(o0, o1, o2, 0.f);
}

// ---------------------------------------------------------------------------
// Persistent node kernel: 512 threads, 8 autonomous pairs, dynamic queue.
// fp16 X (single), fp16 hi/lo weights (in-CTA converted, coalesced reads).
// ---------------------------------------------------------------------------
#define NODE_SMEM_U32 (2*128*XS + 2*64*XS + 128*XS + 128 + 256 + 8)
#define NODE_SMEM_BYTES (NODE_SMEM_U32 * 4)

__global__ void __launch_bounds__(512, 1)
node_mma_kernel(const float* __restrict__ node_emb, const int* __restrict__ graph_id,
                const float* __restrict__ w1raw, const float* __restrict__ b1,
                const float* __restrict__ w2raw,
                const float* __restrict__ w3, const float* __restrict__ b3,
                float* __restrict__ out_node, int N, int U)
{
    extern __shared__ uint32_t su[];
    uint32_t* sW1h = su;                        // [128][XS] fp16x2
    uint32_t* sW1l = sW1h + 128 * XS;
    uint32_t* sW2h = sW1l + 128 * XS;           // [64][XS]
    uint32_t* sW2l = sW2h + 64 * XS;
    uint32_t* sX   = sW2l + 64 * XS;            // [128][XS] fp16x2; merge aliases pair rows
    float*    sB1  = (float*)(sX + 128 * XS);   // [128]
    float*    sW3  = sB1 + 128;                 // [64][4]
    int*      sNU  = (int*)(sW3 + 256);         // [8] next-unit per pair

    const int tid  = threadIdx.x;
    const int lane = tid & 31;
    const int w    = tid >> 5;       // 0..15
    const int p    = w >> 1;         // pair 0..7
    const int h    = w & 1;          // half
    const int g    = lane >> 2;
    const int tg   = lane & 3;
    const int r0   = p * 16;
    const int u    = tid & 63;       // thread within pair
    const int barid = p + 1;
    const int rloc = g + (h ? 8 : 0);           // local row this warp finalizes
    float* mrg = (float*)(sX + p * 1088);       // 4KB inside own pair's sX rows

    // ---- one-time staging: fp32 weights -> fp16 hi/lo smem (coalesced) ----
    for (int i = tid; i < 128 * 64; i += 512) {
        int kp = i >> 7, n = i & 127;               // consecutive tid -> consecutive n
        float f0 = w1raw[(2 * kp) * 128 + n];
        float f1 = w1raw[(2 * kp + 1) * 128 + n];
        __half h0 = __float2half_rn(f0);
        __half h1 = __float2half_rn(f1);
        __half2 hv = __halves2half2(h0, h1);
        sW1h[n * XS + kp] = *(uint32_t*)&hv;
        sW1l[n * XS + kp] = pkh2(f0 - __half2float(h0), f1 - __half2float(h1));
    }
    for (int i = tid; i < 64 * 64; i += 512) {
        int kp = i >> 6, n = i & 63;
        float f0 = w2raw[(2 * kp) * 64 + n];
        float f1 = w2raw[(2 * kp + 1) * 64 + n];
        __half h0 = __float2half_rn(f0);
        __half h1 = __float2half_rn(f1);
        __half2 hv = __halves2half2(h0, h1);
        sW2h[n * XS + kp] = *(uint32_t*)&hv;
        sW2l[n * XS + kp] = pkh2(f0 - __half2float(h0), f1 - __half2float(h1));
    }
    if (tid < 128) sB1[tid] = b1[tid];
    else if (tid >= 256 && tid < 320) ((float4*)sW3)[tid - 256] = ((const float4*)w3)[tid - 256];
    const float b30 = b3[0], b31 = b3[1], b32 = b3[2], b33 = b3[3];

    // ---- prologue: stage this pair's first unit ----
    int unit = blockIdx.x * 8 + p;
    if (unit < U) {
        const int gbase = unit * 16;
        #pragma unroll
        for (int it = 0; it < 8; it++) {
            int idx = it * 64 + u;
            int rl  = idx >> 5;              // 0..15
            int q   = idx & 31;
            int gn  = gbase + rl;
            float4 v = (gn < N) ? ((const float4*)(node_emb + (size_t)gn * 128))[q]
                                : make_float4(0.f, 0.f, 0.f, 0.f);
            *(uint2*)&sX[(r0 + rl) * XS + 2 * q] =
                make_uint2(pkh2(v.x, v.y), pkh2(v.z, v.w));
        }
    }
    __syncthreads();   // only block-wide sync

    while (unit < U) {
        const int gbase = unit * 16;
        const int grow = gbase + rloc;
        const int gid = graph_id[(grow < N) ? grow : (N - 1)];

        // grab next unit early; latency hidden under L1 MMAs
        if (h == 0 && lane == 0) sNU[p] = atomicAdd(&g_ctr, 1);

        // ---- Layer 1: 8 n-tiles (global nt = 8h+j), 8 k-steps, 2 MMAs each ----
        float acc[8][4];
        #pragma unroll
        for (int j = 0; j < 8; j++)
            #pragma unroll
            for (int q = 0; q < 4; q++) acc[j][q] = 0.f;

        const uint32_t* x0 = &sX[(r0 + g) * XS];
        const uint32_t* x1 = &sX[(r0 + g + 8) * XS];

        #pragma unroll
        for (int s = 0; s < 8; s++) {
            const int o = s * 8 + tg;
            uint32_t aH[4] = { x0[o], x1[o], x0[o + 4], x1[o + 4] };
            #pragma unroll
            for (int j = 0; j < 8; j++) {
                const int nrow = ((8 * h + j) * 8 + g) * XS;
                uint32_t bh0 = sW1h[nrow + o], bh1 = sW1h[nrow + o + 4];
                uint32_t bl0 = sW1l[nrow + o], bl1 = sW1l[nrow + o + 4];
                MMAF16(acc[j], aH, bh0, bh1);
                MMAF16(acc[j], aH, bl0, bl1);
            }
        }
        PAIR_BAR(barid);   // barA: pair done reading its sX rows; sNU visible

        // ---- prefetch next unit's X into registers ----
        const int  nunit = sNU[p];
        const bool nv    = nunit < U;
        float4 xp[8];
        if (nv) {
            const int nbase = nunit * 16;
            #pragma unroll
            for (int it = 0; it < 8; it++) {
                int idx = it * 64 + u;
                int gn  = nbase + (idx >> 5);
                xp[it] = (gn < N) ? ((const float4*)(node_emb + (size_t)gn * 128))[idx & 31]
                                  : make_float4(0.f, 0.f, 0.f, 0.f);
            }
        }

        // ---- epilogue 1 (registers): bias+relu -> fp16 A2 frags ----
        uint32_t a2[4][4];
        #pragma unroll
        for (int s2 = 0; s2 < 4; s2++) {
            int cA = (4 * h + s2) * 16 + tg * 2;
            int cB = cA + 8;
            float bA0 = sB1[cA], bA1 = sB1[cA + 1];
            float bB0 = sB1[cB], bB1 = sB1[cB + 1];
            a2[s2][0] = pkh2(fmaxf(acc[2 * s2][0] + bA0, 0.f),
                             fmaxf(acc[2 * s2][1] + bA1, 0.f));
            a2[s2][1] = pkh2(fmaxf(acc[2 * s2][2] + bA0, 0.f),
                             fmaxf(acc[2 * s2][3] + bA1, 0.f));
            a2[s2][2] = pkh2(fmaxf(acc[2 * s2 + 1][0] + bB0, 0.f),
                             fmaxf(acc[2 * s2 + 1][1] + bB1, 0.f));
            a2[s2][3] = pkh2(fmaxf(acc[2 * s2 + 1][2] + bB0, 0.f),
                             fmaxf(acc[2 * s2 + 1][3] + bB1, 0.f));
        }

        // ---- Layer 2: all 8 n-tiles, local k-half (4 steps), 2 MMAs each ----
        float acc2[8][4];
        #pragma unroll
        for (int j = 0; j < 8; j++)
            #pragma unroll
            for (int q = 0; q < 4; q++) acc2[j][q] = 0.f;

        #pragma unroll
        for (int s = 0; s < 4; s++) {
            const int o = (4 * h + s) * 8 + tg;
            #pragma unroll
            for (int j = 0; j < 8; j++) {
                const int nrow = (j * 8 + g) * XS;
                uint32_t bh0 = sW2h[nrow + o], bh1 = sW2h[nrow + o + 4];
                uint32_t bl0 = sW2l[nrow + o], bl1 = sW2l[nrow + o + 4];
                MMAF16(acc2[j], a2[s], bh0, bh1);
                MMAF16(acc2[j], a2[s], bl0, bl1);
            }
        }

        // ---- zb prefetch for this warp's row (L2 hit, hidden by merge) ----
        float2 zbv[8];
        {
            const float2* zp2 = (const float2*)(g_zb + gid * 64);
            #pragma unroll
            for (int nt = 0; nt < 8; nt++) zbv[nt] = zp2[nt * 4 + tg];
        }

        // ---- balanced merge: h0 stores rB-half, h1 stores rA-half ----
        {
            float* dstp = mrg + (h ? 512 : 0);
            int qo = h ? 0 : 2;
            #pragma unroll
            for (int j = 0; j < 8; j++) {
                dstp[(j * 2 + 0) * 32 + lane] = acc2[j][qo + 0];
                dstp[(j * 2 + 1) * 32 + lane] = acc2[j][qo + 1];
            }
        }
        PAIR_BAR(barid);   // barB

        // ---- each warp finalizes its own row ----
        {
            const float* srcp = mrg + (h ? 0 : 512);
            int qo = h ? 2 : 0;
            float o0 = 0.f, o1 = 0.f, o2 = 0.f, o3 = 0.f;
            #pragma unroll
            for (int nt = 0; nt < 8; nt++) {
                float v0 = acc2[nt][qo + 0] + srcp[(nt * 2 + 0) * 32 + lane];
                float v1 = acc2[nt][qo + 1] + srcp[(nt * 2 + 1) * 32 + lane];
                float hv0 = fmaxf(v0 + zbv[nt].x, 0.f);
                float hv1 = fmaxf(v1 + zbv[nt].y, 0.f);
                int c0 = nt * 8 + tg * 2;
                float4 w0 = *(const float4*)&sW3[c0 * 4];
                float4 w1 = *(const float4*)&sW3[(c0 + 1) * 4];
                o0 = fmaf(hv0, w0.x, fmaf(hv1, w1.x, o0));
                o1 = fmaf(hv0, w0.y, fmaf(hv1, w1.y, o1));
                o2 = fmaf(hv0, w0.z, fmaf(hv1, w1.z, o2));
                o3 = fmaf(hv0, w0.w, fmaf(hv1, w1.w, o3));
            }
            #pragma unroll
            for (int d = 1; d <= 2; d <<= 1) {
                o0 += __shfl_xor_sync(0xFFFFFFFF, o0, d);
                o1 += __shfl_xor_sync(0xFFFFFFFF, o1, d);
                o2 += __shfl_xor_sync(0xFFFFFFFF, o2, d);
                o3 += __shfl_xor_sync(0xFFFFFFFF, o3, d);
            }
            if (tg == 0 && grow < N)
                *(float4*)&out_node[(size_t)grow * 4] =
                    make_float4(o0 + b30, o1 + b31, o2 + b32, o3 + b33);
        }
        PAIR_BAR(barid);   // barC: both warps' merge reads complete

        // ---- stage next X (single fp16 array; sX rows free after barC) ----
        if (nv) {
            #pragma unroll
            for (int it = 0; it < 8; it++) {
                int idx = it * 64 + u;
                int rl  = idx >> 5;
                int q   = idx & 31;
                float4 v = xp[it];
                *(uint2*)&sX[(r0 + rl) * XS + 2 * q] =
                    make_uint2(pkh2(v.x, v.y), pkh2(v.z, v.w));
            }
        }
        PAIR_BAR(barid);   // barD: staging done before next L1
        unit = nunit;
    }
}

// ---------------------------------------------------------------------------
// Edge gather: 4 edges/thread. gid8 L1-cached; table L2-only (.cg);
// src/dst + stores streaming (.cs).
// ---------------------------------------------------------------------------
__global__ void edge_gather_kernel(const int* __restrict__ src, const int* __restrict__ dst,
                                   float* __restrict__ out_edge, int E)
{
    int e = (blockIdx.x * blockDim.x + threadIdx.x) * 4;
    if (e >= E) return;
    if (e + 4 <= E) {
        int4 s = __ldcs((const int4*)(src + e));
        int4 d = __ldcs((const int4*)(dst + e));
        int gs0 = g_gid8[s.x], gs1 = g_gid8[s.y], gs2 = g_gid8[s.z], gs3 = g_gid8[s.w];
        int gd0 = g_gid8[d.x], gd1 = g_gid8[d.y], gd2 = g_gid8[d.z], gd3 = g_gid8[d.w];
        float4 t0 = __ldcg(&g_table[gs0 * MAXB + gd0]);
        float4 t1 = __ldcg(&g_table[gs1 * MAXB + gd1]);
        float4 t2 = __ldcg(&g_table[gs2 * MAXB + gd2]);
        float4 t3 = __ldcg(&g_table[gs3 * MAXB + gd3]);
        float* o = out_edge + (size_t)e * 3;
        __stcs((float4*)o,     make_float4(t0.x, t0.y, t0.z, t1.x));
        __stcs((float4*)o + 1, make_float4(t1.y, t1.z, t2.x, t2.y));
        __stcs((float4*)o + 2, make_float4(t2.z, t3.x, t3.y, t3.z));
    } else {
        for (int q = e; q < E; q++) {
            float4 t = __ldcg(&g_table[g_gid8[src[q]] * MAXB + g_gid8[dst[q]]]);
            out_edge[(size_t)q * 3 + 0] = t.x;
            out_edge[(size_t)q * 3 + 1] = t.y;
            out_edge[(size_t)q * 3 + 2] = t.z;
        }
    }
}

// ---------------------------------------------------------------------------
extern "C" void kernel_launch(void* const* d_in, const int* in_sizes, int n_in,
                              void* d_out, int out_size)
{
    const float* z        = (const float*)d_in[0];
    const float* node_emb = (const float*)d_in[1];
    const int*   graph_id = (const int*)  d_in[2];
    const int*   src      = (const int*)  d_in[3];
    const int*   dst      = (const int*)  d_in[4];
    const float* lp_w  = (const float*)d_in[5];
    const float* lp_b  = (const float*)d_in[6];
    const float* nep_w = (const float*)d_in[7];
    const float* nep_b = (const float*)d_in[8];
    const float* nd1_w = (const float*)d_in[9];
    const float* nd1_b = (const float*)d_in[10];
    const float* nd2_w = (const float*)d_in[11];
    const float* nd2_b = (const float*)d_in[12];
    const float* ed1_w = (const float*)d_in[13];
    const float* ed1_b = (const float*)d_in[14];
    const float* ed2_w = (const float*)d_in[15];
    const float* ed2_b = (const float*)d_in[16];
    const float* en1_w = (const float*)d_in[17];
    const float* en1_b = (const float*)d_in[18];
    const float* en2_w = (const float*)d_in[19];
    const float* en2_b = (const float*)d_in[20];
    const float* st1_w = (const float*)d_in[21];
    const float* st1_b = (const float*)d_in[22];
    const float* st2_w = (const float*)d_in[23];
    const float* st2_b = (const float*)d_in[24];

    const int B = in_sizes[0] / 32;
    const int N = in_sizes[1] / 128;
    const int E = in_sizes[3];

    float* out        = (float*)d_out;
    float* out_node   = out;
    float* out_edge   = out + (size_t)N * 4;
    float* out_energy = out + (size_t)N * 4 + (size_t)E * 3;
    float* out_stress = out_energy + (size_t)B * 2;

    cudaFuncSetAttribute(node_mma_kernel, cudaFuncAttributeMaxDynamicSharedMemorySize,
                         NODE_SMEM_BYTES);

    prep_kernel<<<B, 256>>>(z, lp_w, lp_b, nd1_w, nd1_b, ed1_w,
                            en1_w, en1_b, en2_w, en2_b,
                            st1_w, st1_b, st2_w, st2_b,
                            graph_id, N, out_energy, out_stress, B);

    edge_table_kernel<<<B, 256>>>(ed1_b, ed2_w, ed2_b);

    const int U = (N + 15) / 16;
    node_mma_kernel<<<NODE_GRID, 512, NODE_SMEM_BYTES>>>(node_emb, graph_id,
                                                         nep_w, nep_b, nd1_w,
                                                         nd2_w, nd2_b,
                                                         out_node, N, U);

    const int eth = (E + 3) / 4;
    edge_gather_kernel<<<(eth + 255) / 256, 256>>>(src, dst, out_edge, E);
}

// round 13
// speedup vs baseline: 1.2645x; 1.0336x over previous
#include <cuda_runtime.h>
#include <cuda_bf16.h>
#include <cuda_fp16.h>
#include <cstdint>

// ---------------------------------------------------------------------------
// CrystalDecoder on GB300 (sm_103a via compute_103 PTX -> HMMA mma.sync only)
// Node path: 16-warp pair-autonomous fp16 mma.sync GEMM, 2-term weight-only
//            compensation, fragment-layout weights (1 LDS.128 + 2 MMA).
// Edge path: 256x256 lookup table + uint8-gid gather with cache-policy split.
// ---------------------------------------------------------------------------

#define MAXB 256

__device__ float  g_zb[MAXB * 64];      // z_proj @ nd1_w + nd1_b
__device__ float  g_As[MAXB * 64];
__device__ float  g_Bd[MAXB * 64];
__device__ float4 g_table[MAXB * MAXB];
__device__ int    g_ctr;                // dynamic work-queue ticket
__device__ uint8_t g_gid8[262144];      // uint8 graph_id (fits L1)

#define XS 68
#define NODE_GRID 148
#define NPAIRS (NODE_GRID * 8)

#define MMAF16(c, a, b0, b1) \
    asm volatile("mma.sync.aligned.m16n8k16.row.col.f32.f16.f16.f32 " \
        "{%0,%1,%2,%3}, {%4,%5,%6,%7}, {%8,%9}, {%0,%1,%2,%3};" \
        : "+f"((c)[0]), "+f"((c)[1]), "+f"((c)[2]), "+f"((c)[3]) \
        : "r"((a)[0]), "r"((a)[1]), "r"((a)[2]), "r"((a)[3]), "r"(b0), "r"(b1))

#define PAIR_BAR(id) asm volatile("bar.sync %0, 64;" :: "r"(id) : "memory")

__device__ __forceinline__ uint32_t pkh2(float a, float b) {
    __half2 t = __floats2half2_rn(a, b);
    return *(uint32_t*)&t;
}

// fp16 hi + fp16 residual for a pair of fp32 values
__device__ __forceinline__ void hsplit2(float f0, float f1, uint32_t& hi, uint32_t& lo) {
    __half h0 = __float2half_rn(f0);
    __half h1 = __float2half_rn(f1);
    __half2 hv = __halves2half2(h0, h1);
    hi = *(uint32_t*)&hv;
    lo = pkh2(f0 - __half2float(h0), f1 - __half2float(h1));
}

// ---------------------------------------------------------------------------
// Per-graph prep (256 threads, k-split GEMV) + gid8 + queue reset. grid = B.
// ---------------------------------------------------------------------------
__global__ void __launch_bounds__(256)
prep_kernel(const float* __restrict__ z,
            const float* __restrict__ lp_w, const float* __restrict__ lp_b,
            const float* __restrict__ nd1_w, const float* __restrict__ nd1_b,
            const float* __restrict__ ed1_w,
            const float* __restrict__ en1_w, const float* __restrict__ en1_b,
            const float* __restrict__ en2_w, const float* __restrict__ en2_b,
            const float* __restrict__ st1_w, const float* __restrict__ st1_b,
            const float* __restrict__ st2_w, const float* __restrict__ st2_b,
            const int* __restrict__ graph_id, int N,
            float* __restrict__ out_energy, float* __restrict__ out_stress,
            int B)
{
    const int b = blockIdx.x;
    const int t = threadIdx.x;
    __shared__ float zrow[32];
    __shared__ float zp[128];
    __shared__ float eh[64], sh[64];

    if (b == 0 && t == 0) g_ctr = NPAIRS;

    for (int i = b * 256 + t; i < N; i += B * 256)
        g_gid8[i] = (uint8_t)graph_id[i];

    if (t < 32) zrow[t] = z[b * 32 + t];
    __syncthreads();
    if (t < 128) {
        float acc = lp_b[t];
        #pragma unroll
        for (int k = 0; k < 32; k++) acc = fmaf(zrow[k], lp_w[k * 128 + t], acc);
        zp[t] = fmaxf(acc, 0.f);
    } else if (t < 192) {
        int o = t - 128;
        float a1 = en1_b[o], a2 = st1_b[o];
        #pragma unroll
        for (int k = 0; k < 32; k++) {
            float zv = zrow[k];
            a1 = fmaf(zv, en1_w[k * 64 + o], a1);
            a2 = fmaf(zv, st1_w[k * 64 + o], a2);
        }
        eh[o] = fmaxf(a1, 0.f);
        sh[o] = fmaxf(a2, 0.f);
    }
    __syncthreads();

    {
        const int o = t >> 2;
        const int q = t & 3;
        const int k0 = q * 32;
        float as = 0.f, bd = 0.f, zb = (q == 0) ? nd1_b[o] : 0.f;
        #pragma unroll 8
        for (int ki = 0; ki < 32; ki++) {
            int k = k0 + ki;
            float zv = zp[k];
            as = fmaf(zv, ed1_w[k * 64 + o], as);
            bd = fmaf(zv, ed1_w[(128 + k) * 64 + o], bd);
            zb = fmaf(zv, nd1_w[k * 64 + o], zb);
        }
        #pragma unroll
        for (int d = 1; d <= 2; d <<= 1) {
            as += __shfl_xor_sync(0xFFFFFFFF, as, d);
            bd += __shfl_xor_sync(0xFFFFFFFF, bd, d);
            zb += __shfl_xor_sync(0xFFFFFFFF, zb, d);
        }
        if (q == 0) {
            g_As[b * 64 + o] = as;
            g_Bd[b * 64 + o] = bd;
            g_zb[b * 64 + o] = zb;
        }
    }

    if (t < 2) {
        float a = en2_b[t];
        #pragma unroll 8
        for (int k = 0; k < 64; k++) a = fmaf(eh[k], en2_w[k * 2 + t], a);
        out_energy[b * 2 + t] = a;
    }
    if (t >= 16 && t < 25) {
        int j = t - 16;
        float a = st2_b[j];
        #pragma unroll 8
        for (int k = 0; k < 64; k++) a = fmaf(sh[k], st2_w[k * 9 + j], a);
        out_stress[b * 9 + j] = a;
    }
}

// ---------------------------------------------------------------------------
// Edge table
// ---------------------------------------------------------------------------
__global__ void edge_table_kernel(const float* __restrict__ ed1_b,
                                  const float* __restrict__ ed2_w,
                                  const float* __restrict__ ed2_b)
{
    const int gs = blockIdx.x;
    const int gd = threadIdx.x;
    __shared__ float sAs[64], sb1[64], sw2[64 * 3], sb2[3];
    const int t = threadIdx.x;
    if (t < 64) { sAs[t] = g_As[gs * 64 + t]; sb1[t] = ed1_b[t]; }
    if (t >= 64 && t < 64 + 192) sw2[t - 64] = ed2_w[t - 64];
    if (t < 3) sb2[t] = ed2_b[t];
    __syncthreads();

    float o0 = sb2[0], o1 = sb2[1], o2 = sb2[2];
    const float4* bd4 = (const float4*)(&g_Bd[gd * 64]);
    #pragma unroll
    for (int k4 = 0; k4 < 16; k4++) {
        float4 bv = bd4[k4];
        int k = k4 * 4;
        float h;
        h = fmaxf(sAs[k + 0] + bv.x + sb1[k + 0], 0.f);
        o0 = fmaf(h, sw2[(k + 0) * 3 + 0], o0); o1 = fmaf(h, sw2[(k + 0) * 3 + 1], o1); o2 = fmaf(h, sw2[(k + 0) * 3 + 2], o2);
        h = fmaxf(sAs[k + 1] + bv.y + sb1[k + 1], 0.f);
        o0 = fmaf(h, sw2[(k + 1) * 3 + 0], o0); o1 = fmaf(h, sw2[(k + 1) * 3 + 1], o1); o2 = fmaf(h, sw2[(k + 1) * 3 + 2], o2);
        h = fmaxf(sAs[k + 2] + bv.z + sb1[k + 2], 0.f);
        o0 = fmaf(h, sw2[(k + 2) * 3 + 0], o0); o1 = fmaf(h, sw2[(k + 2) * 3 + 1], o1); o2 = fmaf(h, sw2[(k + 2) * 3 + 2], o2);
        h = fmaxf(sAs[k + 3] + bv.w + sb1[k + 3], 0.f);
        o0 = fmaf(h, sw2[(k + 3) * 3 + 0], o0); o1 = fmaf(h, sw2[(k + 3) * 3 + 1], o1); o2 = fmaf(h, sw2[(k + 3) * 3 + 2], o2);
    }
    g_table[gs * MAXB + gd] = make_float4(o0, o1, o2, 0.f);
}

// ---------------------------------------------------------------------------
// Persistent node kernel: 512 threads, 8 autonomous pairs, dynamic queue.
// fp16 X (single), fragment-layout fp16 hi/lo weights (in-CTA converted).
// sW1f[(nt*8+s)*32+lane] = {bh0,bh1,bl0,bl1} for n=nt*8+g, k0=16s+2tg, k1=k0+8.
// ---------------------------------------------------------------------------
#define NODE_SMEM_U32 (4096*4 + 2048*4 + 128*XS + 128 + 256 + 8)
#define NODE_SMEM_BYTES (NODE_SMEM_U32 * 4)

__global__ void __launch_bounds__(512, 1)
node_mma_kernel(const float* __restrict__ node_emb, const int* __restrict__ graph_id,
                const float* __restrict__ w1raw, const float* __restrict__ b1,
                const float* __restrict__ w2raw,
                const float* __restrict__ w3, const float* __restrict__ b3,
                float* __restrict__ out_node, int N, int U)
{
    extern __shared__ uint32_t su[];
    uint4*    sW1f = (uint4*)su;                // [16*8*32]
    uint4*    sW2f = sW1f + 4096;               // [8*8*32]
    uint32_t* sX   = su + 4096 * 4 + 2048 * 4;  // [128][XS] fp16x2; merge aliases pair rows
    float*    sB1  = (float*)(sX + 128 * XS);   // [128]
    float*    sW3  = sB1 + 128;                 // [64][4]
    int*      sNU  = (int*)(sW3 + 256);         // [8] next-unit per pair

    const int tid  = threadIdx.x;
    const int lane = tid & 31;
    const int w    = tid >> 5;       // 0..15
    const int p    = w >> 1;         // pair 0..7
    const int h    = w & 1;          // half
    const int g    = lane >> 2;
    const int tg   = lane & 3;
    const int r0   = p * 16;
    const int u    = tid & 63;       // thread within pair
    const int barid = p + 1;
    const int rloc = g + (h ? 8 : 0);           // local row this warp finalizes
    float* mrg = (float*)(sX + p * 1088);       // 4KB inside own pair's sX rows

    // ---- one-time staging: fp32 weights -> fragment-layout fp16 hi/lo ----
    for (int i = tid; i < 4096; i += 512) {
        int li = i & 31, si = (i >> 5) & 7, nti = i >> 8;
        int n  = nti * 8 + (li >> 2);
        int k0 = 16 * si + 2 * (li & 3);
        int k1 = k0 + 8;
        uint32_t bh0, bl0, bh1, bl1;
        hsplit2(w1raw[k0 * 128 + n], w1raw[(k0 + 1) * 128 + n], bh0, bl0);
        hsplit2(w1raw[k1 * 128 + n], w1raw[(k1 + 1) * 128 + n], bh1, bl1);
        sW1f[i] = make_uint4(bh0, bh1, bl0, bl1);
    }
    for (int i = tid; i < 2048; i += 512) {
        int li = i & 31, si = (i >> 5) & 7, nti = i >> 8;
        int n  = nti * 8 + (li >> 2);    // < 64
        int k0 = 16 * si + 2 * (li & 3);
        int k1 = k0 + 8;
        uint32_t bh0, bl0, bh1, bl1;
        hsplit2(w2raw[k0 * 64 + n], w2raw[(k0 + 1) * 64 + n], bh0, bl0);
        hsplit2(w2raw[k1 * 64 + n], w2raw[(k1 + 1) * 64 + n], bh1, bl1);
        sW2f[i] = make_uint4(bh0, bh1, bl0, bl1);
    }
    if (tid < 128) sB1[tid] = b1[tid];
    else if (tid >= 256 && tid < 320) ((float4*)sW3)[tid - 256] = ((const float4*)w3)[tid - 256];
    const float b30 = b3[0], b31 = b3[1], b32 = b3[2], b33 = b3[3];

    // ---- prologue: stage this pair's first unit ----
    int unit = blockIdx.x * 8 + p;
    if (unit < U) {
        const int gbase = unit * 16;
        #pragma unroll
        for (int it = 0; it < 8; it++) {
            int idx = it * 64 + u;
            int rl  = idx >> 5;              // 0..15
            int q   = idx & 31;
            int gn  = gbase + rl;
            float4 v = (gn < N) ? ((const float4*)(node_emb + (size_t)gn * 128))[q]
                                : make_float4(0.f, 0.f, 0.f, 0.f);
            *(uint2*)&sX[(r0 + rl) * XS + 2 * q] =
                make_uint2(pkh2(v.x, v.y), pkh2(v.z, v.w));
        }
    }
    __syncthreads();   // only block-wide sync

    while (unit < U) {
        const int gbase = unit * 16;
        const int grow = gbase + rloc;
        const int gid = graph_id[(grow < N) ? grow : (N - 1)];

        // grab next unit early; latency hidden under L1 MMAs
        if (h == 0 && lane == 0) sNU[p] = atomicAdd(&g_ctr, 1);

        // ---- Layer 1: 8 n-tiles (global nt = 8h+j), 8 k-steps ----
        float acc[8][4];
        #pragma unroll
        for (int j = 0; j < 8; j++)
            #pragma unroll
            for (int q = 0; q < 4; q++) acc[j][q] = 0.f;

        const uint32_t* x0 = &sX[(r0 + g) * XS];
        const uint32_t* x1 = &sX[(r0 + g + 8) * XS];

        #pragma unroll
        for (int s = 0; s < 8; s++) {
            const int o = s * 8 + tg;
            uint32_t aH[4] = { x0[o], x1[o], x0[o + 4], x1[o + 4] };
            #pragma unroll
            for (int j = 0; j < 8; j++) {
                uint4 b = sW1f[((8 * h + j) * 8 + s) * 32 + lane];
                MMAF16(acc[j], aH, b.x, b.y);
                MMAF16(acc[j], aH, b.z, b.w);
            }
        }
        PAIR_BAR(barid);   // barA: pair done reading its sX rows; sNU visible

        // ---- prefetch next unit's X into registers ----
        const int  nunit = sNU[p];
        const bool nv    = nunit < U;
        float4 xp[8];
        if (nv) {
            const int nbase = nunit * 16;
            #pragma unroll
            for (int it = 0; it < 8; it++) {
                int idx = it * 64 + u;
                int gn  = nbase + (idx >> 5);
                xp[it] = (gn < N) ? ((const float4*)(node_emb + (size_t)gn * 128))[idx & 31]
                                  : make_float4(0.f, 0.f, 0.f, 0.f);
            }
        }

        // ---- epilogue 1 (registers): bias+relu -> fp16 A2 frags ----
        uint32_t a2[4][4];
        #pragma unroll
        for (int s2 = 0; s2 < 4; s2++) {
            int cA = (4 * h + s2) * 16 + tg * 2;
            int cB = cA + 8;
            float bA0 = sB1[cA], bA1 = sB1[cA + 1];
            float bB0 = sB1[cB], bB1 = sB1[cB + 1];
            a2[s2][0] = pkh2(fmaxf(acc[2 * s2][0] + bA0, 0.f),
                             fmaxf(acc[2 * s2][1] + bA1, 0.f));
            a2[s2][1] = pkh2(fmaxf(acc[2 * s2][2] + bA0, 0.f),
                             fmaxf(acc[2 * s2][3] + bA1, 0.f));
            a2[s2][2] = pkh2(fmaxf(acc[2 * s2 + 1][0] + bB0, 0.f),
                             fmaxf(acc[2 * s2 + 1][1] + bB1, 0.f));
            a2[s2][3] = pkh2(fmaxf(acc[2 * s2 + 1][2] + bB0, 0.f),
                             fmaxf(acc[2 * s2 + 1][3] + bB1, 0.f));
        }

        // ---- Layer 2: all 8 n-tiles, local k-half (4 steps) ----
        float acc2[8][4];
        #pragma unroll
        for (int j = 0; j < 8; j++)
            #pragma unroll
            for (int q = 0; q < 4; q++) acc2[j][q] = 0.f;

        #pragma unroll
        for (int s = 0; s < 4; s++) {
            const int sg = 4 * h + s;
            #pragma unroll
            for (int j = 0; j < 8; j++) {
                uint4 b = sW2f[(j * 8 + sg) * 32 + lane];
                MMAF16(acc2[j], a2[s], b.x, b.y);
                MMAF16(acc2[j], a2[s], b.z, b.w);
            }
        }

        // ---- zb prefetch for this warp's row (L2 hit, hidden by merge) ----
        float2 zbv[8];
        {
            const float2* zp2 = (const float2*)(g_zb + gid * 64);
            #pragma unroll
            for (int nt = 0; nt < 8; nt++) zbv[nt] = zp2[nt * 4 + tg];
        }

        // ---- balanced merge: h0 stores rB-half, h1 stores rA-half ----
        {
            float* dstp = mrg + (h ? 512 : 0);
            int qo = h ? 0 : 2;
            #pragma unroll
            for (int j = 0; j < 8; j++) {
                dstp[(j * 2 + 0) * 32 + lane] = acc2[j][qo + 0];
                dstp[(j * 2 + 1) * 32 + lane] = acc2[j][qo + 1];
            }
        }
        PAIR_BAR(barid);   // barB

        // ---- each warp finalizes its own row ----
        {
            const float* srcp = mrg + (h ? 0 : 512);
            int qo = h ? 2 : 0;
            float o0 = 0.f, o1 = 0.f, o2 = 0.f, o3 = 0.f;
            #pragma unroll
            for (int nt = 0; nt < 8; nt++) {
                float v0 = acc2[nt][qo + 0] + srcp[(nt * 2 + 0) * 32 + lane];
                float v1 = acc2[nt][qo + 1] + srcp[(nt * 2 + 1) * 32 + lane];
                float hv0 = fmaxf(v0 + zbv[nt].x, 0.f);
                float hv1 = fmaxf(v1 + zbv[nt].y, 0.f);
                int c0 = nt * 8 + tg * 2;
                float4 w0 = *(const float4*)&sW3[c0 * 4];
                float4 w1 = *(const float4*)&sW3[(c0 + 1) * 4];
                o0 = fmaf(hv0, w0.x, fmaf(hv1, w1.x, o0));
                o1 = fmaf(hv0, w0.y, fmaf(hv1, w1.y, o1));
                o2 = fmaf(hv0, w0.z, fmaf(hv1, w1.z, o2));
                o3 = fmaf(hv0, w0.w, fmaf(hv1, w1.w, o3));
            }
            #pragma unroll
            for (int d = 1; d <= 2; d <<= 1) {
                o0 += __shfl_xor_sync(0xFFFFFFFF, o0, d);
                o1 += __shfl_xor_sync(0xFFFFFFFF, o1, d);
                o2 += __shfl_xor_sync(0xFFFFFFFF, o2, d);
                o3 += __shfl_xor_sync(0xFFFFFFFF, o3, d);
            }
            if (tg == 0 && grow < N)
                *(float4*)&out_node[(size_t)grow * 4] =
                    make_float4(o0 + b30, o1 + b31, o2 + b32, o3 + b33);
        }
        PAIR_BAR(barid);   // barC: both warps' merge reads complete

        // ---- stage next X (single fp16 array; sX rows free after barC) ----
        if (nv) {
            #pragma unroll
            for (int it = 0; it < 8; it++) {
                int idx = it * 64 + u;
                int rl  = idx >> 5;
                int q   = idx & 31;
                float4 v = xp[it];
                *(uint2*)&sX[(r0 + rl) * XS + 2 * q] =
                    make_uint2(pkh2(v.x, v.y), pkh2(v.z, v.w));
            }
        }
        PAIR_BAR(barid);   // barD: staging done before next L1
        unit = nunit;
    }
}

// ---------------------------------------------------------------------------
// Edge gather: 4 edges/thread. gid8 L1-cached; table L2-only (.cg);
// src/dst + stores streaming (.cs).
// ---------------------------------------------------------------------------
__global__ void edge_gather_kernel(const int* __restrict__ src, const int* __restrict__ dst,
                                   float* __restrict__ out_edge, int E)
{
    int e = (blockIdx.x * blockDim.x + threadIdx.x) * 4;
    if (e >= E) return;
    if (e + 4 <= E) {
        int4 s = __ldcs((const int4*)(src + e));
        int4 d = __ldcs((const int4*)(dst + e));
        int gs0 = g_gid8[s.x], gs1 = g_gid8[s.y], gs2 = g_gid8[s.z], gs3 = g_gid8[s.w];
        int gd0 = g_gid8[d.x], gd1 = g_gid8[d.y], gd2 = g_gid8[d.z], gd3 = g_gid8[d.w];
        float4 t0 = __ldcg(&g_table[gs0 * MAXB + gd0]);
        float4 t1 = __ldcg(&g_table[gs1 * MAXB + gd1]);
        float4 t2 = __ldcg(&g_table[gs2 * MAXB + gd2]);
        float4 t3 = __ldcg(&g_table[gs3 * MAXB + gd3]);
        float* o = out_edge + (size_t)e * 3;
        __stcs((float4*)o,     make_float4(t0.x, t0.y, t0.z, t1.x));
        __stcs((float4*)o + 1, make_float4(t1.y, t1.z, t2.x, t2.y));
        __stcs((float4*)o + 2, make_float4(t2.z, t3.x, t3.y, t3.z));
    } else {
        for (int q = e; q < E; q++) {
            float4 t = __ldcg(&g_table[g_gid8[src[q]] * MAXB + g_gid8[dst[q]]]);
            out_edge[(size_t)q * 3 + 0] = t.x;
            out_edge[(size_t)q * 3 + 1] = t.y;
            out_edge[(size_t)q * 3 + 2] = t.z;
        }
    }
}

// ---------------------------------------------------------------------------
extern "C" void kernel_launch(void* const* d_in, const int* in_sizes, int n_in,
                              void* d_out, int out_size)
{
    const float* z        = (const float*)d_in[0];
    const float* node_emb = (const float*)d_in[1];
    const int*   graph_id = (const int*)  d_in[2];
    const int*   src      = (const int*)  d_in[3];
    const int*   dst      = (const int*)  d_in[4];
    const float* lp_w  = (const float*)d_in[5];
    const float* lp_b  = (const float*)d_in[6];
    const float* nep_w = (const float*)d_in[7];
    const float* nep_b = (const float*)d_in[8];
    const float* nd1_w = (const float*)d_in[9];
    const float* nd1_b = (const float*)d_in[10];
    const float* nd2_w = (const float*)d_in[11];
    const float* nd2_b = (const float*)d_in[12];
    const float* ed1_w = (const float*)d_in[13];
    const float* ed1_b = (const float*)d_in[14];
    const float* ed2_w = (const float*)d_in[15];
    const float* ed2_b = (const float*)d_in[16];
    const float* en1_w = (const float*)d_in[17];
    const float* en1_b = (const float*)d_in[18];
    const float* en2_w = (const float*)d_in[19];
    const float* en2_b = (const float*)d_in[20];
    const float* st1_w = (const float*)d_in[21];
    const float* st1_b = (const float*)d_in[22];
    const float* st2_w = (const float*)d_in[23];
    const float* st2_b = (const float*)d_in[24];

    const int B = in_sizes[0] / 32;
    const int N = in_sizes[1] / 128;
    const int E = in_sizes[3];

    float* out        = (float*)d_out;
    float* out_node   = out;
    float* out_edge   = out + (size_t)N * 4;
    float* out_energy = out + (size_t)N * 4 + (size_t)E * 3;
    float* out_stress = out_energy + (size_t)B * 2;

    cudaFuncSetAttribute(node_mma_kernel, cudaFuncAttributeMaxDynamicSharedMemorySize,
                         NODE_SMEM_BYTES);

    prep_kernel<<<B, 256>>>(z, lp_w, lp_b, nd1_w, nd1_b, ed1_w,
                            en1_w, en1_b, en2_w, en2_b,
                            st1_w, st1_b, st2_w, st2_b,
                            graph_id, N, out_energy, out_stress, B);

    edge_table_kernel<<<B, 256>>>(ed1_b, ed2_w, ed2_b);

    const int U = (N + 15) / 16;
    node_mma_kernel<<<NODE_GRID, 512, NODE_SMEM_BYTES>>>(node_emb, graph_id,
                                                         nep_w, nep_b, nd1_w,
                                                         nd2_w, nd2_b,
                                                         out_node, N, U);

    const int eth = (E + 3) / 4;
    edge_gather_kernel<<<(eth + 255) / 256, 256>>>(src, dst, out_edge, E);
}

// round 14
// speedup vs baseline: 1.2966x; 1.0254x over previous
#include <cuda_runtime.h>
#include <cuda_bf16.h>
#include <cuda_fp16.h>
#include <cstdint>

// ---------------------------------------------------------------------------
// CrystalDecoder on GB300 (sm_103a via compute_103 PTX -> HMMA mma.sync only)
// Node path: 16-warp pair-autonomous fp16 mma.sync GEMM, 2-term weight-only
//            compensation, fragment-layout weights (1 LDS.128 + 2 MMA).
// Edge path: 256x256 lookup table + uint8-gid gather, OVERLAPPED with node
//            via CUDA-graph stream fork.
// ---------------------------------------------------------------------------

#define MAXB 256

__device__ float  g_zb[MAXB * 64];      // z_proj @ nd1_w + nd1_b
__device__ float  g_As[MAXB * 64];
__device__ float  g_Bd[MAXB * 64];
__device__ float4 g_table[MAXB * MAXB];
__device__ int    g_ctr;                // dynamic work-queue ticket
__device__ uint8_t g_gid8[262144];      // uint8 graph_id (fits L1)

#define XS 68
#define NODE_GRID 148
#define NPAIRS (NODE_GRID * 8)

#define MMAF16(c, a, b0, b1) \
    asm volatile("mma.sync.aligned.m16n8k16.row.col.f32.f16.f16.f32 " \
        "{%0,%1,%2,%3}, {%4,%5,%6,%7}, {%8,%9}, {%0,%1,%2,%3};" \
        : "+f"((c)[0]), "+f"((c)[1]), "+f"((c)[2]), "+f"((c)[3]) \
        : "r"((a)[0]), "r"((a)[1]), "r"((a)[2]), "r"((a)[3]), "r"(b0), "r"(b1))

#define PAIR_BAR(id) asm volatile("bar.sync %0, 64;" :: "r"(id) : "memory")

__device__ __forceinline__ uint32_t pkh2(float a, float b) {
    __half2 t = __floats2half2_rn(a, b);
    return *(uint32_t*)&t;
}

__device__ __forceinline__ void hsplit2(float f0, float f1, uint32_t& hi, uint32_t& lo) {
    __half h0 = __float2half_rn(f0);
    __half h1 = __float2half_rn(f1);
    __half2 hv = __halves2half2(h0, h1);
    hi = *(uint32_t*)&hv;
    lo = pkh2(f0 - __half2float(h0), f1 - __half2float(h1));
}

// ---------------------------------------------------------------------------
// Per-graph prep (256 threads, k-split GEMV) + gid8 + queue reset. grid = B.
// ---------------------------------------------------------------------------
__global__ void __launch_bounds__(256)
prep_kernel(const float* __restrict__ z,
            const float* __restrict__ lp_w, const float* __restrict__ lp_b,
            const float* __restrict__ nd1_w, const float* __restrict__ nd1_b,
            const float* __restrict__ ed1_w,
            const float* __restrict__ en1_w, const float* __restrict__ en1_b,
            const float* __restrict__ en2_w, const float* __restrict__ en2_b,
            const float* __restrict__ st1_w, const float* __restrict__ st1_b,
            const float* __restrict__ st2_w, const float* __restrict__ st2_b,
            const int* __restrict__ graph_id, int N,
            float* __restrict__ out_energy, float* __restrict__ out_stress,
            int B)
{
    const int b = blockIdx.x;
    const int t = threadIdx.x;
    __shared__ float zrow[32];
    __shared__ float zp[128];
    __shared__ float eh[64], sh[64];

    if (b == 0 && t == 0) g_ctr = NPAIRS;

    for (int i = b * 256 + t; i < N; i += B * 256)
        g_gid8[i] = (uint8_t)graph_id[i];

    if (t < 32) zrow[t] = z[b * 32 + t];
    __syncthreads();
    if (t < 128) {
        float acc = lp_b[t];
        #pragma unroll
        for (int k = 0; k < 32; k++) acc = fmaf(zrow[k], lp_w[k * 128 + t], acc);
        zp[t] = fmaxf(acc, 0.f);
    } else if (t < 192) {
        int o = t - 128;
        float a1 = en1_b[o], a2 = st1_b[o];
        #pragma unroll
        for (int k = 0; k < 32; k++) {
            float zv = zrow[k];
            a1 = fmaf(zv, en1_w[k * 64 + o], a1);
            a2 = fmaf(zv, st1_w[k * 64 + o], a2);
        }
        eh[o] = fmaxf(a1, 0.f);
        sh[o] = fmaxf(a2, 0.f);
    }
    __syncthreads();

    {
        const int o = t >> 2;
        const int q = t & 3;
        const int k0 = q * 32;
        float as = 0.f, bd = 0.f, zb = (q == 0) ? nd1_b[o] : 0.f;
        #pragma unroll 8
        for (int ki = 0; ki < 32; ki++) {
            int k = k0 + ki;
            float zv = zp[k];
            as = fmaf(zv, ed1_w[k * 64 + o], as);
            bd = fmaf(zv, ed1_w[(128 + k) * 64 + o], bd);
            zb = fmaf(zv, nd1_w[k * 64 + o], zb);
        }
        #pragma unroll
        for (int d = 1; d <= 2; d <<= 1) {
            as += __shfl_xor_sync(0xFFFFFFFF, as, d);
            bd += __shfl_xor_sync(0xFFFFFFFF, bd, d);
            zb += __shfl_xor_sync(0xFFFFFFFF, zb, d);
        }
        if (q == 0) {
            g_As[b * 64 + o] = as;
            g_Bd[b * 64 + o] = bd;
            g_zb[b * 64 + o] = zb;
        }
    }

    if (t < 2) {
        float a = en2_b[t];
        #pragma unroll 8
        for (int k = 0; k < 64; k++) a = fmaf(eh[k], en2_w[k * 2 + t], a);
        out_energy[b * 2 + t] = a;
    }
    if (t >= 16 && t < 25) {
        int j = t - 16;
        float a = st2_b[j];
        #pragma unroll 8
        for (int k = 0; k < 64; k++) a = fmaf(sh[k], st2_w[k * 9 + j], a);
        out_stress[b * 9 + j] = a;
    }
}

// ---------------------------------------------------------------------------
// Edge table
// ---------------------------------------------------------------------------
__global__ void edge_table_kernel(const float* __restrict__ ed1_b,
                                  const float* __restrict__ ed2_w,
                                  const float* __restrict__ ed2_b)
{
    const int gs = blockIdx.x;
    const int gd = threadIdx.x;
    __shared__ float sAs[64], sb1[64], sw2[64 * 3], sb2[3];
    const int t = threadIdx.x;
    if (t < 64) { sAs[t] = g_As[gs * 64 + t]; sb1[t] = ed1_b[t]; }
    if (t >= 64 && t < 64 + 192) sw2[t - 64] = ed2_w[t - 64];
    if (t < 3) sb2[t] = ed2_b[t];
    __syncthreads();

    float o0 = sb2[0], o1 = sb2[1], o2 = sb2[2];
    const float4* bd4 = (const float4*)(&g_Bd[gd * 64]);
    #pragma unroll
    for (int k4 = 0; k4 < 16; k4++) {
        float4 bv = bd4[k4];
        int k = k4 * 4;
        float h;
        h = fmaxf(sAs[k + 0] + bv.x + sb1[k + 0], 0.f);
        o0 = fmaf(h, sw2[(k + 0) * 3 + 0], o0); o1 = fmaf(h, sw2[(k + 0) * 3 + 1], o1); o2 = fmaf(h, sw2[(k + 0) * 3 + 2], o2);
        h = fmaxf(sAs[k + 1] + bv.y + sb1[k + 1], 0.f);
        o0 = fmaf(h, sw2[(k + 1) * 3 + 0], o0); o1 = fmaf(h, sw2[(k + 1) * 3 + 1], o1); o2 = fmaf(h, sw2[(k + 1) * 3 + 2], o2);
        h = fmaxf(sAs[k + 2] + bv.z + sb1[k + 2], 0.f);
        o0 = fmaf(h, sw2[(k + 2) * 3 + 0], o0); o1 = fmaf(h, sw2[(k + 2) * 3 + 1], o1); o2 = fmaf(h, sw2[(k + 2) * 3 + 2], o2);
        h = fmaxf(sAs[k + 3] + bv.w + sb1[k + 3], 0.f);
        o0 = fmaf(h, sw2[(k + 3) * 3 + 0], o0); o1 = fmaf(h, sw2[(k + 3) * 3 + 1], o1); o2 = fmaf(h, sw2[(k + 3) * 3 + 2], o2);
    }
    g_table[gs * MAXB + gd] = make_float4(o0, o1, o2, 0.f);
}

// ---------------------------------------------------------------------------
// Persistent node kernel: 512 threads, 8 autonomous pairs, dynamic queue.
// ---------------------------------------------------------------------------
#define NODE_SMEM_U32 (4096*4 + 2048*4 + 128*XS + 128 + 256 + 8)
#define NODE_SMEM_BYTES (NODE_SMEM_U32 * 4)

__global__ void __launch_bounds__(512, 1)
node_mma_kernel(const float* __restrict__ node_emb, const int* __restrict__ graph_id,
                const float* __restrict__ w1raw, const float* __restrict__ b1,
                const float* __restrict__ w2raw,
                const float* __restrict__ w3, const float* __restrict__ b3,
                float* __restrict__ out_node, int N, int U)
{
    extern __shared__ uint32_t su[];
    uint4*    sW1f = (uint4*)su;                // [16*8*32]
    uint4*    sW2f = sW1f + 4096;               // [8*8*32]
    uint32_t* sX   = su + 4096 * 4 + 2048 * 4;  // [128][XS] fp16x2; merge aliases pair rows
    float*    sB1  = (float*)(sX + 128 * XS);   // [128]
    float*    sW3  = sB1 + 128;                 // [64][4]
    int*      sNU  = (int*)(sW3 + 256);         // [8] next-unit per pair

    const int tid  = threadIdx.x;
    const int lane = tid & 31;
    const int w    = tid >> 5;
    const int p    = w >> 1;
    const int h    = w & 1;
    const int g    = lane >> 2;
    const int tg   = lane & 3;
    const int r0   = p * 16;
    const int u    = tid & 63;
    const int barid = p + 1;
    const int rloc = g + (h ? 8 : 0);
    float* mrg = (float*)(sX + p * 1088);

    // ---- one-time staging: fp32 weights -> fragment-layout fp16 hi/lo ----
    for (int i = tid; i < 4096; i += 512) {
        int li = i & 31, si = (i >> 5) & 7, nti = i >> 8;
        int n  = nti * 8 + (li >> 2);
        int k0 = 16 * si + 2 * (li & 3);
        int k1 = k0 + 8;
        uint32_t bh0, bl0, bh1, bl1;
        hsplit2(w1raw[k0 * 128 + n], w1raw[(k0 + 1) * 128 + n], bh0, bl0);
        hsplit2(w1raw[k1 * 128 + n], w1raw[(k1 + 1) * 128 + n], bh1, bl1);
        sW1f[i] = make_uint4(bh0, bh1, bl0, bl1);
    }
    for (int i = tid; i < 2048; i += 512) {
        int li = i & 31, si = (i >> 5) & 7, nti = i >> 8;
        int n  = nti * 8 + (li >> 2);
        int k0 = 16 * si + 2 * (li & 3);
        int k1 = k0 + 8;
        uint32_t bh0, bl0, bh1, bl1;
        hsplit2(w2raw[k0 * 64 + n], w2raw[(k0 + 1) * 64 + n], bh0, bl0);
        hsplit2(w2raw[k1 * 64 + n], w2raw[(k1 + 1) * 64 + n], bh1, bl1);
        sW2f[i] = make_uint4(bh0, bh1, bl0, bl1);
    }
    if (tid < 128) sB1[tid] = b1[tid];
    else if (tid >= 256 && tid < 320) ((float4*)sW3)[tid - 256] = ((const float4*)w3)[tid - 256];
    const float b30 = b3[0], b31 = b3[1], b32 = b3[2], b33 = b3[3];

    // ---- prologue: stage this pair's first unit ----
    int unit = blockIdx.x * 8 + p;
    if (unit < U) {
        const int gbase = unit * 16;
        #pragma unroll
        for (int it = 0; it < 8; it++) {
            int idx = it * 64 + u;
            int rl  = idx >> 5;
            int q   = idx & 31;
            int gn  = gbase + rl;
            float4 v = (gn < N) ? ((const float4*)(node_emb + (size_t)gn * 128))[q]
                                : make_float4(0.f, 0.f, 0.f, 0.f);
            *(uint2*)&sX[(r0 + rl) * XS + 2 * q] =
                make_uint2(pkh2(v.x, v.y), pkh2(v.z, v.w));
        }
    }
    __syncthreads();

    while (unit < U) {
        const int gbase = unit * 16;
        const int grow = gbase + rloc;
        const int gid = graph_id[(grow < N) ? grow : (N - 1)];

        if (h == 0 && lane == 0) sNU[p] = atomicAdd(&g_ctr, 1);

        // ---- Layer 1 ----
        float acc[8][4];
        #pragma unroll
        for (int j = 0; j < 8; j++)
            #pragma unroll
            for (int q = 0; q < 4; q++) acc[j][q] = 0.f;

        const uint32_t* x0 = &sX[(r0 + g) * XS];
        const uint32_t* x1 = &sX[(r0 + g + 8) * XS];

        #pragma unroll
        for (int s = 0; s < 8; s++) {
            const int o = s * 8 + tg;
            uint32_t aH[4] = { x0[o], x1[o], x0[o + 4], x1[o + 4] };
            #pragma unroll
            for (int j = 0; j < 8; j++) {
                uint4 b = sW1f[((8 * h + j) * 8 + s) * 32 + lane];
                MMAF16(acc[j], aH, b.x, b.y);
                MMAF16(acc[j], aH, b.z, b.w);
            }
        }
        PAIR_BAR(barid);   // barA

        const int  nunit = sNU[p];
        const bool nv    = nunit < U;
        float4 xp[8];
        if (nv) {
            const int nbase = nunit * 16;
            #pragma unroll
            for (int it = 0; it < 8; it++) {
                int idx = it * 64 + u;
                int gn  = nbase + (idx >> 5);
                xp[it] = (gn < N) ? ((const float4*)(node_emb + (size_t)gn * 128))[idx & 31]
                                  : make_float4(0.f, 0.f, 0.f, 0.f);
            }
        }

        // ---- epilogue 1 -> fp16 A2 frags ----
        uint32_t a2[4][4];
        #pragma unroll
        for (int s2 = 0; s2 < 4; s2++) {
            int cA = (4 * h + s2) * 16 + tg * 2;
            int cB = cA + 8;
            float bA0 = sB1[cA], bA1 = sB1[cA + 1];
            float bB0 = sB1[cB], bB1 = sB1[cB + 1];
            a2[s2][0] = pkh2(fmaxf(acc[2 * s2][0] + bA0, 0.f),
                             fmaxf(acc[2 * s2][1] + bA1, 0.f));
            a2[s2][1] = pkh2(fmaxf(acc[2 * s2][2] + bA0, 0.f),
                             fmaxf(acc[2 * s2][3] + bA1, 0.f));
            a2[s2][2] = pkh2(fmaxf(acc[2 * s2 + 1][0] + bB0, 0.f),
                             fmaxf(acc[2 * s2 + 1][1] + bB1, 0.f));
            a2[s2][3] = pkh2(fmaxf(acc[2 * s2 + 1][2] + bB0, 0.f),
                             fmaxf(acc[2 * s2 + 1][3] + bB1, 0.f));
        }

        // ---- Layer 2 ----
        float acc2[8][4];
        #pragma unroll
        for (int j = 0; j < 8; j++)
            #pragma unroll
            for (int q = 0; q < 4; q++) acc2[j][q] = 0.f;

        #pragma unroll
        for (int s = 0; s < 4; s++) {
            const int sg = 4 * h + s;
            #pragma unroll
            for (int j = 0; j < 8; j++) {
                uint4 b = sW2f[(j * 8 + sg) * 32 + lane];
                MMAF16(acc2[j], a2[s], b.x, b.y);
                MMAF16(acc2[j], a2[s], b.z, b.w);
            }
        }

        // ---- zb prefetch ----
        float2 zbv[8];
        {
            const float2* zp2 = (const float2*)(g_zb + gid * 64);
            #pragma unroll
            for (int nt = 0; nt < 8; nt++) zbv[nt] = zp2[nt * 4 + tg];
        }

        // ---- balanced merge ----
        {
            float* dstp = mrg + (h ? 512 : 0);
            int qo = h ? 0 : 2;
            #pragma unroll
            for (int j = 0; j < 8; j++) {
                dstp[(j * 2 + 0) * 32 + lane] = acc2[j][qo + 0];
                dstp[(j * 2 + 1) * 32 + lane] = acc2[j][qo + 1];
            }
        }
        PAIR_BAR(barid);   // barB

        {
            const float* srcp = mrg + (h ? 0 : 512);
            int qo = h ? 2 : 0;
            float o0 = 0.f, o1 = 0.f, o2 = 0.f, o3 = 0.f;
            #pragma unroll
            for (int nt = 0; nt < 8; nt++) {
                float v0 = acc2[nt][qo + 0] + srcp[(nt * 2 + 0) * 32 + lane];
                float v1 = acc2[nt][qo + 1] + srcp[(nt * 2 + 1) * 32 + lane];
                float hv0 = fmaxf(v0 + zbv[nt].x, 0.f);
                float hv1 = fmaxf(v1 + zbv[nt].y, 0.f);
                int c0 = nt * 8 + tg * 2;
                float4 w0 = *(const float4*)&sW3[c0 * 4];
                float4 w1 = *(const float4*)&sW3[(c0 + 1) * 4];
                o0 = fmaf(hv0, w0.x, fmaf(hv1, w1.x, o0));
                o1 = fmaf(hv0, w0.y, fmaf(hv1, w1.y, o1));
                o2 = fmaf(hv0, w0.z, fmaf(hv1, w1.z, o2));
                o3 = fmaf(hv0, w0.w, fmaf(hv1, w1.w, o3));
            }
            #pragma unroll
            for (int d = 1; d <= 2; d <<= 1) {
                o0 += __shfl_xor_sync(0xFFFFFFFF, o0, d);
                o1 += __shfl_xor_sync(0xFFFFFFFF, o1, d);
                o2 += __shfl_xor_sync(0xFFFFFFFF, o2, d);
                o3 += __shfl_xor_sync(0xFFFFFFFF, o3, d);
            }
            if (tg == 0 && grow < N)
                *(float4*)&out_node[(size_t)grow * 4] =
                    make_float4(o0 + b30, o1 + b31, o2 + b32, o3 + b33);
        }
        PAIR_BAR(barid);   // barC

        if (nv) {
            #pragma unroll
            for (int it = 0; it < 8; it++) {
                int idx = it * 64 + u;
                int rl  = idx >> 5;
                int q   = idx & 31;
                float4 v = xp[it];
                *(uint2*)&sX[(r0 + rl) * XS + 2 * q] =
                    make_uint2(pkh2(v.x, v.y), pkh2(v.z, v.w));
            }
        }
        PAIR_BAR(barid);   // barD
        unit = nunit;
    }
}

// ---------------------------------------------------------------------------
// Edge gather: 4 edges/thread; cache-policy split.
// ---------------------------------------------------------------------------
__global__ void edge_gather_kernel(const int* __restrict__ src, const int* __restrict__ dst,
                                   float* __restrict__ out_edge, int E)
{
    int e = (blockIdx.x * blockDim.x + threadIdx.x) * 4;
    if (e >= E) return;
    if (e + 4 <= E) {
        int4 s = __ldcs((const int4*)(src + e));
        int4 d = __ldcs((const int4*)(dst + e));
        int gs0 = g_gid8[s.x], gs1 = g_gid8[s.y], gs2 = g_gid8[s.z], gs3 = g_gid8[s.w];
        int gd0 = g_gid8[d.x], gd1 = g_gid8[d.y], gd2 = g_gid8[d.z], gd3 = g_gid8[d.w];
        float4 t0 = __ldcg(&g_table[gs0 * MAXB + gd0]);
        float4 t1 = __ldcg(&g_table[gs1 * MAXB + gd1]);
        float4 t2 = __ldcg(&g_table[gs2 * MAXB + gd2]);
        float4 t3 = __ldcg(&g_table[gs3 * MAXB + gd3]);
        float* o = out_edge + (size_t)e * 3;
        __stcs((float4*)o,     make_float4(t0.x, t0.y, t0.z, t1.x));
        __stcs((float4*)o + 1, make_float4(t1.y, t1.z, t2.x, t2.y));
        __stcs((float4*)o + 2, make_float4(t2.z, t3.x, t3.y, t3.z));
    } else {
        for (int q = e; q < E; q++) {
            float4 t = __ldcg(&g_table[g_gid8[src[q]] * MAXB + g_gid8[dst[q]]]);
            out_edge[(size_t)q * 3 + 0] = t.x;
            out_edge[(size_t)q * 3 + 1] = t.y;
            out_edge[(size_t)q * 3 + 2] = t.z;
        }
    }
}

// ---------------------------------------------------------------------------
extern "C" void kernel_launch(void* const* d_in, const int* in_sizes, int n_in,
                              void* d_out, int out_size)
{
    const float* z        = (const float*)d_in[0];
    const float* node_emb = (const float*)d_in[1];
    const int*   graph_id = (const int*)  d_in[2];
    const int*   src      = (const int*)  d_in[3];
    const int*   dst      = (const int*)  d_in[4];
    const float* lp_w  = (const float*)d_in[5];
    const float* lp_b  = (const float*)d_in[6];
    const float* nep_w = (const float*)d_in[7];
    const float* nep_b = (const float*)d_in[8];
    const float* nd1_w = (const float*)d_in[9];
    const float* nd1_b = (const float*)d_in[10];
    const float* nd2_w = (const float*)d_in[11];
    const float* nd2_b = (const float*)d_in[12];
    const float* ed1_w = (const float*)d_in[13];
    const float* ed1_b = (const float*)d_in[14];
    const float* ed2_w = (const float*)d_in[15];
    const float* ed2_b = (const float*)d_in[16];
    const float* en1_w = (const float*)d_in[17];
    const float* en1_b = (const float*)d_in[18];
    const float* en2_w = (const float*)d_in[19];
    const float* en2_b = (const float*)d_in[20];
    const float* st1_w = (const float*)d_in[21];
    const float* st1_b = (const float*)d_in[22];
    const float* st2_w = (const float*)d_in[23];
    const float* st2_b = (const float*)d_in[24];

    const int B = in_sizes[0] / 32;
    const int N = in_sizes[1] / 128;
    const int E = in_sizes[3];

    float* out        = (float*)d_out;
    float* out_node   = out;
    float* out_edge   = out + (size_t)N * 4;
    float* out_energy = out + (size_t)N * 4 + (size_t)E * 3;
    float* out_stress = out_energy + (size_t)B * 2;

    // one-time setup (runs on the uncaptured correctness call)
    static cudaStream_t s_side = nullptr;
    static cudaEvent_t  s_fork = nullptr, s_join = nullptr;
    if (s_side == nullptr) {
        cudaStreamCreateWithFlags(&s_side, cudaStreamNonBlocking);
        cudaEventCreateWithFlags(&s_fork, cudaEventDisableTiming);
        cudaEventCreateWithFlags(&s_join, cudaEventDisableTiming);
        cudaFuncSetAttribute(node_mma_kernel,
                             cudaFuncAttributeMaxDynamicSharedMemorySize,
                             NODE_SMEM_BYTES);
    }

    // prep on main stream (both branches depend on it)
    prep_kernel<<<B, 256>>>(z, lp_w, lp_b, nd1_w, nd1_b, ed1_w,
                            en1_w, en1_b, en2_w, en2_b,
                            st1_w, st1_b, st2_w, st2_b,
                            graph_id, N, out_energy, out_stress, B);

    // fork: edge branch (table -> gather) on side stream
    cudaEventRecord(s_fork, 0);
    cudaStreamWaitEvent(s_side, s_fork, 0);

    edge_table_kernel<<<B, 256, 0, s_side>>>(ed1_b, ed2_w, ed2_b);
    const int eth = (E + 3) / 4;
    edge_gather_kernel<<<(eth + 255) / 256, 256, 0, s_side>>>(src, dst, out_edge, E);
    cudaEventRecord(s_join, s_side);

    // node branch on main stream (concurrent with edge branch)
    const int U = (N + 15) / 16;
    node_mma_kernel<<<NODE_GRID, 512, NODE_SMEM_BYTES>>>(node_emb, graph_id,
                                                         nep_w, nep_b, nd1_w,
                                                         nd2_w, nd2_b,
                                                         out_node, N, U);

    // join
    cudaStreamWaitEvent(0, s_join, 0);
}

// round 16
// speedup vs baseline: 1.3402x; 1.0336x over previous
#include <cuda_runtime.h>
#include <cuda_bf16.h>
#include <cuda_fp16.h>
#include <cstdint>

// ---------------------------------------------------------------------------
// CrystalDecoder on GB300 (sm_103a via compute_103 PTX -> HMMA mma.sync only)
// Node path: 16-warp pair-autonomous fp16 mma.sync GEMM, 2-term weight-only
//            compensation, fragment-layout weights, capped at 112 regs so the
//            edge-gather kernel can co-reside on the same SMs (true overlap).
// Edge path: 256x256 lookup table + uint8-gid gather on a forked stream.
// ---------------------------------------------------------------------------

#define MAXB 256

__device__ float  g_zb[MAXB * 64];      // z_proj @ nd1_w + nd1_b
__device__ float  g_As[MAXB * 64];
__device__ float  g_Bd[MAXB * 64];
__device__ float4 g_table[MAXB * MAXB];
__device__ int    g_ctr;                // dynamic work-queue ticket
__device__ uint8_t g_gid8[262144];      // uint8 graph_id (fits L1)

#define XS 68
#define NODE_GRID 148
#define NPAIRS (NODE_GRID * 8)

#define MMAF16(c, a, b0, b1) \
    asm volatile("mma.sync.aligned.m16n8k16.row.col.f32.f16.f16.f32 " \
        "{%0,%1,%2,%3}, {%4,%5,%6,%7}, {%8,%9}, {%0,%1,%2,%3};" \
        : "+f"((c)[0]), "+f"((c)[1]), "+f"((c)[2]), "+f"((c)[3]) \
        : "r"((a)[0]), "r"((a)[1]), "r"((a)[2]), "r"((a)[3]), "r"(b0), "r"(b1))

#define PAIR_BAR(id) asm volatile("bar.sync %0, 64;" :: "r"(id) : "memory")

__device__ __forceinline__ uint32_t pkh2(float a, float b) {
    __half2 t = __floats2half2_rn(a, b);
    return *(uint32_t*)&t;
}

__device__ __forceinline__ void hsplit2(float f0, float f1, uint32_t& hi, uint32_t& lo) {
    __half h0 = __float2half_rn(f0);
    __half h1 = __float2half_rn(f1);
    __half2 hv = __halves2half2(h0, h1);
    hi = *(uint32_t*)&hv;
    lo = pkh2(f0 - __half2float(h0), f1 - __half2float(h1));
}

// ---------------------------------------------------------------------------
// Per-graph prep (256 threads, k-split GEMV) + gid8 + queue reset. grid = B.
// ---------------------------------------------------------------------------
__global__ void __launch_bounds__(256)
prep_kernel(const float* __restrict__ z,
            const float* __restrict__ lp_w, const float* __restrict__ lp_b,
            const float* __restrict__ nd1_w, const float* __restrict__ nd1_b,
            const float* __restrict__ ed1_w,
            const float* __restrict__ en1_w, const float* __restrict__ en1_b,
            const float* __restrict__ en2_w, const float* __restrict__ en2_b,
            const float* __restrict__ st1_w, const float* __restrict__ st1_b,
            const float* __restrict__ st2_w, const float* __restrict__ st2_b,
            const int* __restrict__ graph_id, int N,
            float* __restrict__ out_energy, float* __restrict__ out_stress,
            int B)
{
    const int b = blockIdx.x;
    const int t = threadIdx.x;
    __shared__ float zrow[32];
    __shared__ float zp[128];
    __shared__ float eh[64], sh[64];

    if (b == 0 && t == 0) g_ctr = NPAIRS;

    for (int i = b * 256 + t; i < N; i += B * 256)
        g_gid8[i] = (uint8_t)graph_id[i];

    if (t < 32) zrow[t] = z[b * 32 + t];
    __syncthreads();
    if (t < 128) {
        float acc = lp_b[t];
        #pragma unroll
        for (int k = 0; k < 32; k++) acc = fmaf(zrow[k], lp_w[k * 128 + t], acc);
        zp[t] = fmaxf(acc, 0.f);
    } else if (t < 192) {
        int o = t - 128;
        float a1 = en1_b[o], a2 = st1_b[o];
        #pragma unroll
        for (int k = 0; k < 32; k++) {
            float zv = zrow[k];
            a1 = fmaf(zv, en1_w[k * 64 + o], a1);
            a2 = fmaf(zv, st1_w[k * 64 + o], a2);
        }
        eh[o] = fmaxf(a1, 0.f);
        sh[o] = fmaxf(a2, 0.f);
    }
    __syncthreads();

    {
        const int o = t >> 2;
        const int q = t & 3;
        const int k0 = q * 32;
        float as = 0.f, bd = 0.f, zb = (q == 0) ? nd1_b[o] : 0.f;
        #pragma unroll 8
        for (int ki = 0; ki < 32; ki++) {
            int k = k0 + ki;
            float zv = zp[k];
            as = fmaf(zv, ed1_w[k * 64 + o], as);
            bd = fmaf(zv, ed1_w[(128 + k) * 64 + o], bd);
            zb = fmaf(zv, nd1_w[k * 64 + o], zb);
        }
        #pragma unroll
        for (int d = 1; d <= 2; d <<= 1) {
            as += __shfl_xor_sync(0xFFFFFFFF, as, d);
            bd += __shfl_xor_sync(0xFFFFFFFF, bd, d);
            zb += __shfl_xor_sync(0xFFFFFFFF, zb, d);
        }
        if (q == 0) {
            g_As[b * 64 + o] = as;
            g_Bd[b * 64 + o] = bd;
            g_zb[b * 64 + o] = zb;
        }
    }

    if (t < 2) {
        float a = en2_b[t];
        #pragma unroll 8
        for (int k = 0; k < 64; k++) a = fmaf(eh[k], en2_w[k * 2 + t], a);
        out_energy[b * 2 + t] = a;
    }
    if (t >= 16 && t < 25) {
        int j = t - 16;
        float a = st2_b[j];
        #pragma unroll 8
        for (int k = 0; k < 64; k++) a = fmaf(sh[k], st2_w[k * 9 + j], a);
        out_stress[b * 9 + j] = a;
    }
}

// ---------------------------------------------------------------------------
// Edge table
// ---------------------------------------------------------------------------
__global__ void edge_table_kernel(const float* __restrict__ ed1_b,
                                  const float* __restrict__ ed2_w,
                                  const float* __restrict__ ed2_b)
{
    const int gs = blockIdx.x;
    const int gd = threadIdx.x;
    __shared__ float sAs[64], sb1[64], sw2[64 * 3], sb2[3];
    const int t = threadIdx.x;
    if (t < 64) { sAs[t] = g_As[gs * 64 + t]; sb1[t] = ed1_b[t]; }
    if (t >= 64 && t < 64 + 192) sw2[t - 64] = ed2_w[t - 64];
    if (t < 3) sb2[t] = ed2_b[t];
    __syncthreads();

    float o0 = sb2[0], o1 = sb2[1], o2 = sb2[2];
    const float4* bd4 = (const float4*)(&g_Bd[gd * 64]);
    #pragma unroll
    for (int k4 = 0; k4 < 16; k4++) {
        float4 bv = bd4[k4];
        int k = k4 * 4;
        float h;
        h = fmaxf(sAs[k + 0] + bv.x + sb1[k + 0], 0.f);
        o0 = fmaf(h, sw2[(k + 0) * 3 + 0], o0); o1 = fmaf(h, sw2[(k + 0) * 3 + 1], o1); o2 = fmaf(h, sw2[(k + 0) * 3 + 2], o2);
        h = fmaxf(sAs[k + 1] + bv.y + sb1[k + 1], 0.f);
        o0 = fmaf(h, sw2[(k + 1) * 3 + 0], o0); o1 = fmaf(h, sw2[(k + 1) * 3 + 1], o1); o2 = fmaf(h, sw2[(k + 1) * 3 + 2], o2);
        h = fmaxf(sAs[k + 2] + bv.z + sb1[k + 2], 0.f);
        o0 = fmaf(h, sw2[(k + 2) * 3 + 0], o0); o1 = fmaf(h, sw2[(k + 2) * 3 + 1], o1); o2 = fmaf(h, sw2[(k + 2) * 3 + 2], o2);
        h = fmaxf(sAs[k + 3] + bv.w + sb1[k + 3], 0.f);
        o0 = fmaf(h, sw2[(k + 3) * 3 + 0], o0); o1 = fmaf(h, sw2[(k + 3) * 3 + 1], o1); o2 = fmaf(h, sw2[(k + 3) * 3 + 2], o2);
    }
    g_table[gs * MAXB + gd] = make_float4(o0, o1, o2, 0.f);
}

// ---------------------------------------------------------------------------
// Persistent node kernel: 512 threads, 8 autonomous pairs, dynamic queue.
// __maxnreg__(112): 112*512 = 57344 regs -> leaves 8192 for a co-resident
// gather block (26*256 = 6656). True kernel-level overlap.
// (135 KB dynamic smem already limits residency to 1 CTA/SM; no launch_bounds.)
// ---------------------------------------------------------------------------
#define NODE_SMEM_U32 (4096*4 + 2048*4 + 128*XS + 128 + 256 + 8)
#define NODE_SMEM_BYTES (NODE_SMEM_U32 * 4)

__global__ void __maxnreg__(112)
node_mma_kernel(const float* __restrict__ node_emb, const int* __restrict__ graph_id,
                const float* __restrict__ w1raw, const float* __restrict__ b1,
                const float* __restrict__ w2raw,
                const float* __restrict__ w3, const float* __restrict__ b3,
                float* __restrict__ out_node, int N, int U)
{
    extern __shared__ uint32_t su[];
    uint4*    sW1f = (uint4*)su;                // [16*8*32]
    uint4*    sW2f = sW1f + 4096;               // [8*8*32]
    uint32_t* sX   = su + 4096 * 4 + 2048 * 4;  // [128][XS] fp16x2; merge aliases pair rows
    float*    sB1  = (float*)(sX + 128 * XS);   // [128]
    float*    sW3  = sB1 + 128;                 // [64][4]
    int*      sNU  = (int*)(sW3 + 256);         // [8] next-unit per pair

    const int tid  = threadIdx.x;
    const int lane = tid & 31;
    const int w    = tid >> 5;
    const int p    = w >> 1;
    const int h    = w & 1;
    const int g    = lane >> 2;
    const int tg   = lane & 3;
    const int r0   = p * 16;
    const int u    = tid & 63;
    const int barid = p + 1;
    const int rloc = g + (h ? 8 : 0);
    float* mrg = (float*)(sX + p * 1088);

    // ---- one-time staging: fp32 weights -> fragment-layout fp16 hi/lo ----
    for (int i = tid; i < 4096; i += 512) {
        int li = i & 31, si = (i >> 5) & 7, nti = i >> 8;
        int n  = nti * 8 + (li >> 2);
        int k0 = 16 * si + 2 * (li & 3);
        int k1 = k0 + 8;
        uint32_t bh0, bl0, bh1, bl1;
        hsplit2(w1raw[k0 * 128 + n], w1raw[(k0 + 1) * 128 + n], bh0, bl0);
        hsplit2(w1raw[k1 * 128 + n], w1raw[(k1 + 1) * 128 + n], bh1, bl1);
        sW1f[i] = make_uint4(bh0, bh1, bl0, bl1);
    }
    for (int i = tid; i < 2048; i += 512) {
        int li = i & 31, si = (i >> 5) & 7, nti = i >> 8;
        int n  = nti * 8 + (li >> 2);
        int k0 = 16 * si + 2 * (li & 3);
        int k1 = k0 + 8;
        uint32_t bh0, bl0, bh1, bl1;
        hsplit2(w2raw[k0 * 64 + n], w2raw[(k0 + 1) * 64 + n], bh0, bl0);
        hsplit2(w2raw[k1 * 64 + n], w2raw[(k1 + 1) * 64 + n], bh1, bl1);
        sW2f[i] = make_uint4(bh0, bh1, bl0, bl1);
    }
    if (tid < 128) sB1[tid] = b1[tid];
    else if (tid >= 256 && tid < 320) ((float4*)sW3)[tid - 256] = ((const float4*)w3)[tid - 256];
    const float b30 = b3[0], b31 = b3[1], b32 = b3[2], b33 = b3[3];

    // ---- prologue: stage this pair's first unit ----
    int unit = blockIdx.x * 8 + p;
    if (unit < U) {
        const int gbase = unit * 16;
        #pragma unroll
        for (int it = 0; it < 8; it++) {
            int idx = it * 64 + u;
            int rl  = idx >> 5;
            int q   = idx & 31;
            int gn  = gbase + rl;
            float4 v = (gn < N) ? ((const float4*)(node_emb + (size_t)gn * 128))[q]
                                : make_float4(0.f, 0.f, 0.f, 0.f);
            *(uint2*)&sX[(r0 + rl) * XS + 2 * q] =
                make_uint2(pkh2(v.x, v.y), pkh2(v.z, v.w));
        }
    }
    __syncthreads();

    while (unit < U) {
        const int gbase = unit * 16;
        const int grow = gbase + rloc;
        const int gid = graph_id[(grow < N) ? grow : (N - 1)];

        if (h == 0 && lane == 0) sNU[p] = atomicAdd(&g_ctr, 1);

        // ---- Layer 1 ----
        float acc[8][4];
        #pragma unroll
        for (int j = 0; j < 8; j++)
            #pragma unroll
            for (int q = 0; q < 4; q++) acc[j][q] = 0.f;

        const uint32_t* x0 = &sX[(r0 + g) * XS];
        const uint32_t* x1 = &sX[(r0 + g + 8) * XS];

        #pragma unroll
        for (int s = 0; s < 8; s++) {
            const int o = s * 8 + tg;
            uint32_t aH[4] = { x0[o], x1[o], x0[o + 4], x1[o + 4] };
            #pragma unroll
            for (int j = 0; j < 8; j++) {
                uint4 b = sW1f[((8 * h + j) * 8 + s) * 32 + lane];
                MMAF16(acc[j], aH, b.x, b.y);
                MMAF16(acc[j], aH, b.z, b.w);
            }
        }
        PAIR_BAR(barid);   // barA

        const int  nunit = sNU[p];
        const bool nv    = nunit < U;
        float4 xp[8];
        if (nv) {
            const int nbase = nunit * 16;
            #pragma unroll
            for (int it = 0; it < 8; it++) {
                int idx = it * 64 + u;
                int gn  = nbase + (idx >> 5);
                xp[it] = (gn < N) ? ((const float4*)(node_emb + (size_t)gn * 128))[idx & 31]
                                  : make_float4(0.f, 0.f, 0.f, 0.f);
            }
        }

        // ---- epilogue 1 -> fp16 A2 frags ----
        uint32_t a2[4][4];
        #pragma unroll
        for (int s2 = 0; s2 < 4; s2++) {
            int cA = (4 * h + s2) * 16 + tg * 2;
            int cB = cA + 8;
            float bA0 = sB1[cA], bA1 = sB1[cA + 1];
            float bB0 = sB1[cB], bB1 = sB1[cB + 1];
            a2[s2][0] = pkh2(fmaxf(acc[2 * s2][0] + bA0, 0.f),
                             fmaxf(acc[2 * s2][1] + bA1, 0.f));
            a2[s2][1] = pkh2(fmaxf(acc[2 * s2][2] + bA0, 0.f),
                             fmaxf(acc[2 * s2][3] + bA1, 0.f));
            a2[s2][2] = pkh2(fmaxf(acc[2 * s2 + 1][0] + bB0, 0.f),
                             fmaxf(acc[2 * s2 + 1][1] + bB1, 0.f));
            a2[s2][3] = pkh2(fmaxf(acc[2 * s2 + 1][2] + bB0, 0.f),
                             fmaxf(acc[2 * s2 + 1][3] + bB1, 0.f));
        }

        // ---- Layer 2 ----
        float acc2[8][4];
        #pragma unroll
        for (int j = 0; j < 8; j++)
            #pragma unroll
            for (int q = 0; q < 4; q++) acc2[j][q] = 0.f;

        #pragma unroll
        for (int s = 0; s < 4; s++) {
            const int sg = 4 * h + s;
            #pragma unroll
            for (int j = 0; j < 8; j++) {
                uint4 b = sW2f[(j * 8 + sg) * 32 + lane];
                MMAF16(acc2[j], a2[s], b.x, b.y);
                MMAF16(acc2[j], a2[s], b.z, b.w);
            }
        }

        // ---- zb prefetch ----
        float2 zbv[8];
        {
            const float2* zp2 = (const float2*)(g_zb + gid * 64);
            #pragma unroll
            for (int nt = 0; nt < 8; nt++) zbv[nt] = zp2[nt * 4 + tg];
        }

        // ---- balanced merge ----
        {
            float* dstp = mrg + (h ? 512 : 0);
            int qo = h ? 0 : 2;
            #pragma unroll
            for (int j = 0; j < 8; j++) {
                dstp[(j * 2 + 0) * 32 + lane] = acc2[j][qo + 0];
                dstp[(j * 2 + 1) * 32 + lane] = acc2[j][qo + 1];
            }
        }
        PAIR_BAR(barid);   // barB

        {
            const float* srcp = mrg + (h ? 0 : 512);
            int qo = h ? 2 : 0;
            float o0 = 0.f, o1 = 0.f, o2 = 0.f, o3 = 0.f;
            #pragma unroll
            for (int nt = 0; nt < 8; nt++) {
                float v0 = acc2[nt][qo + 0] + srcp[(nt * 2 + 0) * 32 + lane];
                float v1 = acc2[nt][qo + 1] + srcp[(nt * 2 + 1) * 32 + lane];
                float hv0 = fmaxf(v0 + zbv[nt].x, 0.f);
                float hv1 = fmaxf(v1 + zbv[nt].y, 0.f);
                int c0 = nt * 8 + tg * 2;
                float4 w0 = *(const float4*)&sW3[c0 * 4];
                float4 w1 = *(const float4*)&sW3[(c0 + 1) * 4];
                o0 = fmaf(hv0, w0.x, fmaf(hv1, w1.x, o0));
                o1 = fmaf(hv0, w0.y, fmaf(hv1, w1.y, o1));
                o2 = fmaf(hv0, w0.z, fmaf(hv1, w1.z, o2));
                o3 = fmaf(hv0, w0.w, fmaf(hv1, w1.w, o3));
            }
            #pragma unroll
            for (int d = 1; d <= 2; d <<= 1) {
                o0 += __shfl_xor_sync(0xFFFFFFFF, o0, d);
                o1 += __shfl_xor_sync(0xFFFFFFFF, o1, d);
                o2 += __shfl_xor_sync(0xFFFFFFFF, o2, d);
                o3 += __shfl_xor_sync(0xFFFFFFFF, o3, d);
            }
            if (tg == 0 && grow < N)
                *(float4*)&out_node[(size_t)grow * 4] =
                    make_float4(o0 + b30, o1 + b31, o2 + b32, o3 + b33);
        }
        PAIR_BAR(barid);   // barC

        if (nv) {
            #pragma unroll
            for (int it = 0; it < 8; it++) {
                int idx = it * 64 + u;
                int rl  = idx >> 5;
                int q   = idx & 31;
                float4 v = xp[it];
                *(uint2*)&sX[(r0 + rl) * XS + 2 * q] =
                    make_uint2(pkh2(v.x, v.y), pkh2(v.z, v.w));
            }
        }
        PAIR_BAR(barid);   // barD
        unit = nunit;
    }
}

// ---------------------------------------------------------------------------
// Edge gather: 4 edges/thread; cache-policy split.
// ---------------------------------------------------------------------------
__global__ void edge_gather_kernel(const int* __restrict__ src, const int* __restrict__ dst,
                                   float* __restrict__ out_edge, int E)
{
    int e = (blockIdx.x * blockDim.x + threadIdx.x) * 4;
    if (e >= E) return;
    if (e + 4 <= E) {
        int4 s = __ldcs((const int4*)(src + e));
        int4 d = __ldcs((const int4*)(dst + e));
        int gs0 = g_gid8[s.x], gs1 = g_gid8[s.y], gs2 = g_gid8[s.z], gs3 = g_gid8[s.w];
        int gd0 = g_gid8[d.x], gd1 = g_gid8[d.y], gd2 = g_gid8[d.z], gd3 = g_gid8[d.w];
        float4 t0 = __ldcg(&g_table[gs0 * MAXB + gd0]);
        float4 t1 = __ldcg(&g_table[gs1 * MAXB + gd1]);
        float4 t2 = __ldcg(&g_table[gs2 * MAXB + gd2]);
        float4 t3 = __ldcg(&g_table[gs3 * MAXB + gd3]);
        float* o = out_edge + (size_t)e * 3;
        __stcs((float4*)o,     make_float4(t0.x, t0.y, t0.z, t1.x));
        __stcs((float4*)o + 1, make_float4(t1.y, t1.z, t2.x, t2.y));
        __stcs((float4*)o + 2, make_float4(t2.z, t3.x, t3.y, t3.z));
    } else {
        for (int q = e; q < E; q++) {
            float4 t = __ldcg(&g_table[g_gid8[src[q]] * MAXB + g_gid8[dst[q]]]);
            out_edge[(size_t)q * 3 + 0] = t.x;
            out_edge[(size_t)q * 3 + 1] = t.y;
            out_edge[(size_t)q * 3 + 2] = t.z;
        }
    }
}

// ---------------------------------------------------------------------------
extern "C" void kernel_launch(void* const* d_in, const int* in_sizes, int n_in,
                              void* d_out, int out_size)
{
    const float* z        = (const float*)d_in[0];
    const float* node_emb = (const float*)d_in[1];
    const int*   graph_id = (const int*)  d_in[2];
    const int*   src      = (const int*)  d_in[3];
    const int*   dst      = (const int*)  d_in[4];
    const float* lp_w  = (const float*)d_in[5];
    const float* lp_b  = (const float*)d_in[6];
    const float* nep_w = (const float*)d_in[7];
    const float* nep_b = (const float*)d_in[8];
    const float* nd1_w = (const float*)d_in[9];
    const float* nd1_b = (const float*)d_in[10];
    const float* nd2_w = (const float*)d_in[11];
    const float* nd2_b = (const float*)d_in[12];
    const float* ed1_w = (const float*)d_in[13];
    const float* ed1_b = (const float*)d_in[14];
    const float* ed2_w = (const float*)d_in[15];
    const float* ed2_b = (const float*)d_in[16];
    const float* en1_w = (const float*)d_in[17];
    const float* en1_b = (const float*)d_in[18];
    const float* en2_w = (const float*)d_in[19];
    const float* en2_b = (const float*)d_in[20];
    const float* st1_w = (const float*)d_in[21];
    const float* st1_b = (const float*)d_in[22];
    const float* st2_w = (const float*)d_in[23];
    const float* st2_b = (const float*)d_in[24];

    const int B = in_sizes[0] / 32;
    const int N = in_sizes[1] / 128;
    const int E = in_sizes[3];

    float* out        = (float*)d_out;
    float* out_node   = out;
    float* out_edge   = out + (size_t)N * 4;
    float* out_energy = out + (size_t)N * 4 + (size_t)E * 3;
    float* out_stress = out_energy + (size_t)B * 2;

    // one-time setup (runs on the uncaptured correctness call)
    static cudaStream_t s_side = nullptr;
    static cudaEvent_t  s_fork = nullptr, s_join = nullptr;
    if (s_side == nullptr) {
        cudaStreamCreateWithFlags(&s_side, cudaStreamNonBlocking);
        cudaEventCreateWithFlags(&s_fork, cudaEventDisableTiming);
        cudaEventCreateWithFlags(&s_join, cudaEventDisableTiming);
        cudaFuncSetAttribute(node_mma_kernel,
                             cudaFuncAttributeMaxDynamicSharedMemorySize,
                             NODE_SMEM_BYTES);
    }

    // prep on main stream (both branches depend on it)
    prep_kernel<<<B, 256>>>(z, lp_w, lp_b, nd1_w, nd1_b, ed1_w,
                            en1_w, en1_b, en2_w, en2_b,
                            st1_w, st1_b, st2_w, st2_b,
                            graph_id, N, out_energy, out_stress, B);

    // fork: edge branch (table -> gather) on side stream
    cudaEventRecord(s_fork, 0);
    cudaStreamWaitEvent(s_side, s_fork, 0);

    edge_table_kernel<<<B, 256, 0, s_side>>>(ed1_b, ed2_w, ed2_b);
    const int eth = (E + 3) / 4;
    edge_gather_kernel<<<(eth + 255) / 256, 256, 0, s_side>>>(src, dst, out_edge, E);
    cudaEventRecord(s_join, s_side);

    // node branch on main stream (concurrent with edge branch)
    const int U = (N + 15) / 16;
    node_mma_kernel<<<NODE_GRID, 512, NODE_SMEM_BYTES>>>(node_emb, graph_id,
                                                         nep_w, nep_b, nd1_w,
                                                         nd2_w, nd2_b,
                                                         out_node, N, U);

    // join
    cudaStreamWaitEvent(0, s_join, 0);
}